// round 1
// baseline (speedup 1.0000x reference)
#include <cuda_runtime.h>
#include <math.h>
#include <stdint.h>

// Problem dims (fixed)
#define NN 4096
#define CC 512
#define HH 128
#define KTOP 3

#define NEG_INF (__int_as_float(0xff800000))

// ---------------- static scratch (no allocations allowed) ----------------
__device__ float g_big[(size_t)NN * NN];      // 64MB: hs2c cos / hc2s
__device__ float g_nc[(size_t)NN * CC];       // 8MB: s2c / logitsT / cosPC
__device__ float g_hidden1[CC * HH];
__device__ float g_hiddenB[CC * HH];
__device__ float g_tmp[NN * HH];
__device__ float g_pshared[NN * HH];
__device__ float g_h[NN * HH];
__device__ float g_hidden2[NN * HH];
__device__ float g_hshared[NN * HH];
__device__ float g_indiv[NN * HH];
__device__ float g_outsum[NN * HH];
__device__ float g_colsum[CC];
__device__ float g_valid1[CC];
__device__ float g_normx[NN];
__device__ float g_normB[CC];
__device__ float g_normh[NN];
__device__ float g_diag[NN];
__device__ float g_norm2[NN];
__device__ float g_valid2[NN];
__device__ float g_colsum2[NN];
__device__ float g_val3[NN * KTOP];
__device__ int   g_idx3[NN * KTOP];

// ---------------- generic tiled SGEMM ----------------
// C[M,Nn] = A ? B  with:
//   TA=0: A row-major [M,K]  (A[m,k])
//   TA=1: A row-major [K,M]  (A[k,m])   (i.e., computes A^T @ ...)
//   TB=0: B row-major [Nn,K] (B[n,k])   (i.e., ... @ B^T)
//   TB=1: B row-major [K,Nn] (B[k,n])
// Epilogue modes:
enum { EP_NONE = 0, EP_BIAS = 1, EP_BIAS_LRELU = 2, EP_COS = 3, EP_ROWSCALE = 4, EP_RESID = 5 };

struct EpiParams {
    int mode;
    int accum;                 // only for EP_BIAS_LRELU
    const float* bias;         // [Nn]
    const float* rowscale;     // [M]
    const float* normA;        // [M]
    const float* normB;        // [Nn]
    const float* validf;       // [Nn] (0/1), may be null
    const float* resid;        // [M,Nn]
};

#define BM 64
#define BN 64
#define BK 32

template <int TA, int TB>
__global__ void gemm_kernel(const float* __restrict__ A, const float* __restrict__ B,
                            float* __restrict__ C, int M, int Nn, int K, EpiParams ep) {
    __shared__ float As[BK][BM + 4];
    __shared__ float Bs[BK][BN + 4];
    const int m0 = blockIdx.y * BM;
    const int n0 = blockIdx.x * BN;
    const int tid = threadIdx.x;
    const int tx = tid & 15;
    const int ty = tid >> 4;

    float acc[4][4];
#pragma unroll
    for (int i = 0; i < 4; i++)
#pragma unroll
        for (int j = 0; j < 4; j++) acc[i][j] = 0.0f;

    for (int k0 = 0; k0 < K; k0 += BK) {
        if (TA == 0) {
#pragma unroll
            for (int l = 0; l < 8; l++) {
                int id = tid + l * 256;
                int k = id & 31, m = id >> 5;
                As[k][m] = A[(size_t)(m0 + m) * K + (k0 + k)];
            }
        } else {
#pragma unroll
            for (int l = 0; l < 8; l++) {
                int id = tid + l * 256;
                int m = id & 63, k = id >> 6;
                As[k][m] = A[(size_t)(k0 + k) * M + (m0 + m)];
            }
        }
        if (TB == 0) {
#pragma unroll
            for (int l = 0; l < 8; l++) {
                int id = tid + l * 256;
                int k = id & 31, n = id >> 5;
                Bs[k][n] = B[(size_t)(n0 + n) * K + (k0 + k)];
            }
        } else {
#pragma unroll
            for (int l = 0; l < 8; l++) {
                int id = tid + l * 256;
                int n = id & 63, k = id >> 6;
                Bs[k][n] = B[(size_t)(k0 + k) * Nn + (n0 + n)];
            }
        }
        __syncthreads();
#pragma unroll
        for (int k = 0; k < BK; k++) {
            float a[4], b[4];
#pragma unroll
            for (int i = 0; i < 4; i++) a[i] = As[k][ty * 4 + i];
#pragma unroll
            for (int j = 0; j < 4; j++) b[j] = Bs[k][tx * 4 + j];
#pragma unroll
            for (int i = 0; i < 4; i++)
#pragma unroll
                for (int j = 0; j < 4; j++) acc[i][j] = fmaf(a[i], b[j], acc[i][j]);
        }
        __syncthreads();
    }

#pragma unroll
    for (int i = 0; i < 4; i++) {
#pragma unroll
        for (int j = 0; j < 4; j++) {
            int m = m0 + ty * 4 + i;
            int n = n0 + tx * 4 + j;
            float v = acc[i][j];
            size_t o = (size_t)m * Nn + n;
            switch (ep.mode) {
                case EP_NONE:
                    C[o] = v;
                    break;
                case EP_BIAS:
                    C[o] = v + ep.bias[n];
                    break;
                case EP_BIAS_LRELU: {
                    float z = v + ep.bias[n];
                    z = z > 0.0f ? z : 0.01f * z;
                    if (ep.accum) C[o] += z; else C[o] = z;
                    break;
                }
                case EP_COS: {
                    float den = ep.normA[m] * ep.normB[n];
                    v = v / (den == 0.0f ? 1.0f : den);
                    if (ep.validf && ep.validf[n] == 0.0f) v = NEG_INF;
                    C[o] = v;
                    break;
                }
                case EP_ROWSCALE:
                    C[o] = v * ep.rowscale[m];
                    break;
                case EP_RESID:
                    C[o] = ep.resid[o] - (v + ep.bias[n]);
                    break;
            }
        }
    }
}

// ---------------- small kernels ----------------
__global__ void colsum_cm_kernel(const float* __restrict__ cm, const float* __restrict__ mv,
                                 float* __restrict__ colsum) {
    int c = blockIdx.x;
    int t = threadIdx.x;
    float s = 0.0f;
    for (int i = t; i < NN; i += 256) s += cm[(size_t)i * CC + c] * mv[i];
    __shared__ float sh[256];
    sh[t] = s;
    __syncthreads();
    for (int o = 128; o > 0; o >>= 1) {
        if (t < o) sh[t] += sh[t + o];
        __syncthreads();
    }
    if (t == 0) colsum[c] = sh[0];
}

__global__ void s2c_kernel(const float* __restrict__ cm, const float* __restrict__ mv,
                           const float* __restrict__ colsum, float* __restrict__ out) {
    int idx = blockIdx.x * blockDim.x + threadIdx.x;
    if (idx >= NN * CC) return;
    int i = idx / CC;
    int c = idx - i * CC;
    float m = cm[idx];
    out[idx] = (m * mv[i]) / (colsum[c] * m + 1.0f);
}

// valid flag from row-sum != 0 of an [M,HH] matrix
__global__ void rowflag_kernel(const float* __restrict__ X, float* __restrict__ validf) {
    int m = blockIdx.x;
    int t = threadIdx.x;  // 128
    __shared__ float sh[128];
    sh[t] = X[(size_t)m * HH + t];
    __syncthreads();
    for (int o = 64; o > 0; o >>= 1) {
        if (t < o) sh[t] += sh[t + o];
        __syncthreads();
    }
    if (t == 0) validf[m] = (sh[0] != 0.0f) ? 1.0f : 0.0f;
}

// row L2 norm of [M,HH]; optionally write "diag" cos value ss/(n*n) (0 if n==0)
__global__ void rownorm_kernel(const float* __restrict__ X, float* __restrict__ norm,
                               float* __restrict__ diag) {
    int m = blockIdx.x;
    int t = threadIdx.x;  // 128
    float v = X[(size_t)m * HH + t];
    __shared__ float sh[128];
    sh[t] = v * v;
    __syncthreads();
    for (int o = 64; o > 0; o >>= 1) {
        if (t < o) sh[t] += sh[t + o];
        __syncthreads();
    }
    if (t == 0) {
        float ss = sh[0];
        float n = sqrtf(ss);
        norm[m] = n;
        if (diag) {
            float den = n * n;
            diag[m] = (den == 0.0f) ? 0.0f : ss / den;
        }
    }
}

__global__ void softmax_rows_kernel(float* __restrict__ buf, int L) {
    int r = blockIdx.x;
    float* row = buf + (size_t)r * L;
    int t = threadIdx.x;  // 256
    __shared__ float sh[256];
    float mx = NEG_INF;
    for (int j = t; j < L; j += 256) mx = fmaxf(mx, row[j]);
    sh[t] = mx;
    __syncthreads();
    for (int o = 128; o > 0; o >>= 1) {
        if (t < o) sh[t] = fmaxf(sh[t], sh[t + o]);
        __syncthreads();
    }
    mx = sh[0];
    __syncthreads();
    float s = 0.0f;
    for (int j = t; j < L; j += 256) s += expf(row[j] - mx);
    sh[t] = s;
    __syncthreads();
    for (int o = 128; o > 0; o >>= 1) {
        if (t < o) sh[t] += sh[t + o];
        __syncthreads();
    }
    float inv = 1.0f / sh[0];
    __syncthreads();
    for (int j = t; j < L; j += 256) row[j] = expf(row[j] - mx) * inv;
}

__global__ void top3_kernel(const float* __restrict__ big, int* __restrict__ idx3,
                            float* __restrict__ val3) {
    int i = blockIdx.x;
    int t = threadIdx.x;  // 128
    const float* row = big + (size_t)i * NN;
    float v0 = NEG_INF, v1 = NEG_INF, v2 = NEG_INF;
    int i0 = 0, i1 = 0, i2 = 0;
    for (int j = t; j < NN; j += 128) {
        float v = (j == i) ? 0.0f : row[j];
        if (v > v0) { v2 = v1; i2 = i1; v1 = v0; i1 = i0; v0 = v; i0 = j; }
        else if (v > v1) { v2 = v1; i2 = i1; v1 = v; i1 = j; }
        else if (v > v2) { v2 = v; i2 = j; }
    }
    __shared__ float sv[384];
    __shared__ int si[384];
    sv[t] = v0; sv[128 + t] = v1; sv[256 + t] = v2;
    si[t] = i0; si[128 + t] = i1; si[256 + t] = i2;
    __syncthreads();
    if (t == 0) {
        for (int k = 0; k < KTOP; k++) {
            float best = NEG_INF;
            int bq = 0;
            for (int q = 0; q < 384; q++)
                if (sv[q] > best) { best = sv[q]; bq = q; }
            val3[i * KTOP + k] = best;
            idx3[i * KTOP + k] = si[bq];
            sv[bq] = NEG_INF;
        }
    }
}

__global__ void zero_kernel(float* __restrict__ a, int n) {
    int i = blockIdx.x * blockDim.x + threadIdx.x;
    if (i < n) a[i] = 0.0f;
}

__global__ void scatter_kernel(const int* __restrict__ idx3, const float* __restrict__ val3,
                               const float* __restrict__ h, float* __restrict__ hidden2,
                               float* __restrict__ colsum2) {
    int i = blockIdx.x;
    int t = threadIdx.x;  // 128
    float hv = h[(size_t)i * HH + t];
#pragma unroll
    for (int k = 0; k < KTOP; k++) {
        int j = idx3[i * KTOP + k];
        float v = val3[i * KTOP + k];
        atomicAdd(&hidden2[(size_t)j * HH + t], v * hv);
        if (t == 0) atomicAdd(&colsum2[j], v);
    }
}

// add diagonal term, compute valid2, apply it, compute norm2
__global__ void diag_valid_kernel(const float* __restrict__ colsum2, const float* __restrict__ diag,
                                  const float* __restrict__ h, float* __restrict__ hidden2,
                                  float* __restrict__ valid2f, float* __restrict__ norm2) {
    int j = blockIdx.x;
    int t = threadIdx.x;  // 128
    float dterm = (colsum2[j] != 0.0f) ? diag[j] : 0.0f;
    float v = hidden2[(size_t)j * HH + t] + dterm * h[(size_t)j * HH + t];
    __shared__ float shs[128];
    __shared__ float shq[128];
    shs[t] = v;
    shq[t] = v * v;
    __syncthreads();
    for (int o = 64; o > 0; o >>= 1) {
        if (t < o) { shs[t] += shs[t + o]; shq[t] += shq[t + o]; }
        __syncthreads();
    }
    float valid = (shs[0] != 0.0f) ? 1.0f : 0.0f;
    hidden2[(size_t)j * HH + t] = v * valid;
    if (t == 0) {
        valid2f[j] = valid;
        norm2[j] = valid * sqrtf(shq[0]);
    }
}

__global__ void final_kernel(const float* __restrict__ outsum, const float* __restrict__ Wout,
                             const float* __restrict__ bout, float* __restrict__ y) {
    int i = blockIdx.x;
    int t = threadIdx.x;  // 128
    __shared__ float sh[128];
    sh[t] = outsum[(size_t)i * HH + t] * Wout[t];
    __syncthreads();
    for (int o = 64; o > 0; o >>= 1) {
        if (t < o) sh[t] += sh[t + o];
        __syncthreads();
    }
    if (t == 0) y[i] = sh[0] + bout[0];
}

// ---------------- host orchestration ----------------
static EpiParams ep_make(int mode) {
    EpiParams e;
    e.mode = mode; e.accum = 0;
    e.bias = nullptr; e.rowscale = nullptr; e.normA = nullptr; e.normB = nullptr;
    e.validf = nullptr; e.resid = nullptr;
    return e;
}

static void launch_gemm(int TA, int TB, const float* A, const float* B, float* C,
                        int M, int Nn, int K, const EpiParams& ep) {
    dim3 grid(Nn / BN, M / BM), block(256);
    if (TA == 0 && TB == 0) gemm_kernel<0, 0><<<grid, block>>>(A, B, C, M, Nn, K, ep);
    else if (TA == 0 && TB == 1) gemm_kernel<0, 1><<<grid, block>>>(A, B, C, M, Nn, K, ep);
    else if (TA == 1 && TB == 1) gemm_kernel<1, 1><<<grid, block>>>(A, B, C, M, Nn, K, ep);
    else gemm_kernel<1, 0><<<grid, block>>>(A, B, C, M, Nn, K, ep);
}

#define SYM(p, s) do { void* _tmp; cudaGetSymbolAddress(&_tmp, s); p = (float*)_tmp; } while (0)

extern "C" void kernel_launch(void* const* d_in, const int* in_sizes, int n_in,
                              void* d_out, int out_size) {
    const float* x = (const float*)d_in[0];
    const float* cm = (const float*)d_in[1];
    const float* mv = (const float*)d_in[2];
    const float* W_ps = (const float*)d_in[3];
    const float* b_ps = (const float*)d_in[4];
    const float* W_psf = (const float*)d_in[5];
    const float* b_psf = (const float*)d_in[6];
    const float* W_psb = (const float*)d_in[7];
    const float* b_psb = (const float*)d_in[8];
    const float* W_hs = (const float*)d_in[9];
    const float* b_hs = (const float*)d_in[10];
    const float* W_hsf = (const float*)d_in[11];
    const float* b_hsf = (const float*)d_in[12];
    const float* W_hsb = (const float*)d_in[13];
    const float* b_hsb = (const float*)d_in[14];
    const float* W_in = (const float*)d_in[15];
    const float* b_in = (const float*)d_in[16];
    const float* W_out = (const float*)d_in[17];
    const float* b_out = (const float*)d_in[18];
    float* y = (float*)d_out;

    float *p_big, *p_nc, *p_hidden1, *p_hiddenB, *p_tmp, *p_pshared, *p_h, *p_hidden2,
        *p_hshared, *p_indiv, *p_outsum, *p_colsum, *p_valid1, *p_normx, *p_normB, *p_normh,
        *p_diag, *p_norm2, *p_valid2, *p_colsum2, *p_val3;
    int* p_idx3;
    SYM(p_big, g_big); SYM(p_nc, g_nc); SYM(p_hidden1, g_hidden1); SYM(p_hiddenB, g_hiddenB);
    SYM(p_tmp, g_tmp); SYM(p_pshared, g_pshared); SYM(p_h, g_h); SYM(p_hidden2, g_hidden2);
    SYM(p_hshared, g_hshared); SYM(p_indiv, g_indiv); SYM(p_outsum, g_outsum);
    SYM(p_colsum, g_colsum); SYM(p_valid1, g_valid1); SYM(p_normx, g_normx);
    SYM(p_normB, g_normB); SYM(p_normh, g_normh); SYM(p_diag, g_diag); SYM(p_norm2, g_norm2);
    SYM(p_valid2, g_valid2); SYM(p_colsum2, g_colsum2); SYM(p_val3, g_val3);
    { void* t; cudaGetSymbolAddress(&t, g_idx3); p_idx3 = (int*)t; }

    // zero scratch needed by scatter (graph-replay safe)
    zero_kernel<<<(NN * HH + 255) / 256, 256>>>(p_hidden2, NN * HH);
    zero_kernel<<<(NN + 255) / 256, 256>>>(p_colsum2, NN);

    // x norms (used by cos(x, hiddenB))
    rownorm_kernel<<<NN, 128>>>(x, p_normx, nullptr);

    // ---- ps branch ----
    colsum_cm_kernel<<<CC, 256>>>(cm, mv, p_colsum);
    s2c_kernel<<<(NN * CC + 255) / 256, 256>>>(cm, mv, p_colsum, p_nc);
    // hidden1 = s2c^T @ x   [C,H]
    launch_gemm(1, 1, p_nc, x, p_hidden1, CC, HH, NN, ep_make(EP_NONE));
    rowflag_kernel<<<CC, 128>>>(p_hidden1, p_valid1);
    // logitsT = hidden1 @ x^T   [C,N]
    launch_gemm(0, 0, p_hidden1, x, p_nc, CC, NN, HH, ep_make(EP_NONE));
    // softmax over stocks (rows of transposed logits)
    softmax_rows_kernel<<<CC, 256>>>(p_nc, NN);
    // hiddenB = s2c2^T @ x, scaled by valid1   [C,H]
    {
        EpiParams e = ep_make(EP_ROWSCALE);
        e.rowscale = p_valid1;
        launch_gemm(0, 1, p_nc, x, p_hiddenB, CC, HH, NN, e);
    }
    rownorm_kernel<<<CC, 128>>>(p_hiddenB, p_normB, nullptr);
    // cos(x, hiddenB) with valid1 mask -> [N,C]
    {
        EpiParams e = ep_make(EP_COS);
        e.normA = p_normx; e.normB = p_normB; e.validf = p_valid1;
        launch_gemm(0, 0, x, p_hiddenB, p_nc, NN, CC, HH, e);
    }
    softmax_rows_kernel<<<NN, 256>>>(p_nc, CC);
    // tmp = c2s @ hiddenB  [N,H]
    launch_gemm(0, 1, p_nc, p_hiddenB, p_tmp, NN, HH, CC, ep_make(EP_NONE));
    // p_shared = tmp @ W_ps^T + b_ps
    {
        EpiParams e = ep_make(EP_BIAS);
        e.bias = b_ps;
        launch_gemm(0, 0, p_tmp, W_ps, p_pshared, NN, HH, HH, e);
    }
    // h = x - (p_shared @ W_ps_back^T + b)
    {
        EpiParams e = ep_make(EP_RESID);
        e.bias = b_psb; e.resid = x;
        launch_gemm(0, 0, p_pshared, W_psb, p_h, NN, HH, HH, e);
    }
    // out = lrelu(p_shared @ W_ps_fore^T + b)
    {
        EpiParams e = ep_make(EP_BIAS_LRELU);
        e.bias = b_psf; e.accum = 0;
        launch_gemm(0, 0, p_pshared, W_psf, p_outsum, NN, HH, HH, e);
    }

    // ---- hs branch ----
    rownorm_kernel<<<NN, 128>>>(p_h, p_normh, p_diag);
    // hs2c = cos(h,h)  [N,N]
    {
        EpiParams e = ep_make(EP_COS);
        e.normA = p_normh; e.normB = p_normh;
        launch_gemm(0, 0, p_h, p_h, p_big, NN, NN, HH, e);
    }
    top3_kernel<<<NN, 128>>>(p_big, p_idx3, p_val3);
    scatter_kernel<<<NN, 128>>>(p_idx3, p_val3, p_h, p_hidden2, p_colsum2);
    diag_valid_kernel<<<NN, 128>>>(p_colsum2, p_diag, p_h, p_hidden2, p_valid2, p_norm2);
    // cos(h, hidden2) with valid2 mask  [N,N]
    {
        EpiParams e = ep_make(EP_COS);
        e.normA = p_normh; e.normB = p_norm2; e.validf = p_valid2;
        launch_gemm(0, 0, p_h, p_hidden2, p_big, NN, NN, HH, e);
    }
    softmax_rows_kernel<<<NN, 256>>>(p_big, NN);
    // tmp = hc2s @ hidden2  [N,H]
    launch_gemm(0, 1, p_big, p_hidden2, p_tmp, NN, HH, NN, ep_make(EP_NONE));
    // h_shared = tmp @ W_hs^T + b
    {
        EpiParams e = ep_make(EP_BIAS);
        e.bias = b_hs;
        launch_gemm(0, 0, p_tmp, W_hs, p_hshared, NN, HH, HH, e);
    }
    // indiv = h - (h_shared @ W_hs_back^T + b)
    {
        EpiParams e = ep_make(EP_RESID);
        e.bias = b_hsb; e.resid = p_h;
        launch_gemm(0, 0, p_hshared, W_hsb, p_indiv, NN, HH, HH, e);
    }
    // out += lrelu(h_shared @ W_hs_fore^T + b)
    {
        EpiParams e = ep_make(EP_BIAS_LRELU);
        e.bias = b_hsf; e.accum = 1;
        launch_gemm(0, 0, p_hshared, W_hsf, p_outsum, NN, HH, HH, e);
    }
    // out += lrelu(indiv @ W_indi^T + b)
    {
        EpiParams e = ep_make(EP_BIAS_LRELU);
        e.bias = b_in; e.accum = 1;
        launch_gemm(0, 0, p_indiv, W_in, p_outsum, NN, HH, HH, e);
    }

    // y = out @ W_out^T + b_out
    final_kernel<<<NN, 128>>>(p_outsum, W_out, b_out, y);
}

// round 2
// speedup vs baseline: 1.6688x; 1.6688x over previous
#include <cuda_runtime.h>
#include <math.h>
#include <stdint.h>

#define NN 4096
#define CC 512
#define HH 128
#define KTOP 3

#define NEG_INF (__int_as_float(0xff800000))

// ---------------- static scratch ----------------
__device__ float g_big[(size_t)NN * NN];
__device__ float g_nc[(size_t)NN * CC];
__device__ float g_hidden1[CC * HH];
__device__ float g_hiddenB[CC * HH];
__device__ float g_tmp[NN * HH];
__device__ float g_pshared[NN * HH];
__device__ float g_h[NN * HH];
__device__ float g_hidden2[NN * HH];
__device__ float g_hshared[NN * HH];
__device__ float g_indiv[NN * HH];
__device__ float g_outsum[NN * HH];
__device__ float g_colsum[CC];
__device__ float g_valid1[CC];
__device__ float g_normx[NN];
__device__ float g_normB[CC];
__device__ float g_normh[NN];
__device__ float g_diag[NN];
__device__ float g_norm2[NN];
__device__ float g_valid2[NN];
__device__ float g_colsum2[NN];

enum { EP_NONE = 0, EP_BIAS = 1, EP_BIAS_LRELU = 2, EP_COS = 3, EP_RESID = 5 };

struct EpiParams {
    int mode;
    int accum;
    const float* bias;
    const float* normA;
    const float* normB;
    const float* validf;
    const float* resid;
};

// ---------------- 128x64 tile GEMM (TA=0, TB=0): C[M,Nn] = A[M,K] @ B[Nn,K]^T ----
__global__ void gemm128_kernel(const float* __restrict__ A, const float* __restrict__ B,
                               float* __restrict__ C, int M, int Nn, int K, EpiParams ep) {
    __shared__ float As[16][128 + 4];
    __shared__ float Bs[16][64 + 4];
    const int m0 = blockIdx.y * 128;
    const int n0 = blockIdx.x * 64;
    const int tid = threadIdx.x;
    const int tx = tid & 15;    // n: 16 groups of 4
    const int ty = tid >> 4;    // m: 16 groups of 8

    float acc[8][4];
#pragma unroll
    for (int i = 0; i < 8; i++)
#pragma unroll
        for (int j = 0; j < 4; j++) acc[i][j] = 0.0f;

    for (int k0 = 0; k0 < K; k0 += 16) {
#pragma unroll
        for (int l = 0; l < 2; l++) {
            int id = tid + l * 256;
            int k4 = id & 3;
            int m = id >> 2;
            float4 v = *(const float4*)&A[(size_t)(m0 + m) * K + k0 + k4 * 4];
            As[k4 * 4 + 0][m] = v.x;
            As[k4 * 4 + 1][m] = v.y;
            As[k4 * 4 + 2][m] = v.z;
            As[k4 * 4 + 3][m] = v.w;
        }
        {
            int k4 = tid & 3;
            int n = tid >> 2;
            float4 v = *(const float4*)&B[(size_t)(n0 + n) * K + k0 + k4 * 4];
            Bs[k4 * 4 + 0][n] = v.x;
            Bs[k4 * 4 + 1][n] = v.y;
            Bs[k4 * 4 + 2][n] = v.z;
            Bs[k4 * 4 + 3][n] = v.w;
        }
        __syncthreads();
#pragma unroll
        for (int k = 0; k < 16; k++) {
            float a[8], b[4];
#pragma unroll
            for (int i = 0; i < 8; i++) a[i] = As[k][ty * 8 + i];
#pragma unroll
            for (int j = 0; j < 4; j++) b[j] = Bs[k][tx * 4 + j];
#pragma unroll
            for (int i = 0; i < 8; i++)
#pragma unroll
                for (int j = 0; j < 4; j++) acc[i][j] = fmaf(a[i], b[j], acc[i][j]);
        }
        __syncthreads();
    }

#pragma unroll
    for (int i = 0; i < 8; i++) {
#pragma unroll
        for (int j = 0; j < 4; j++) {
            int m = m0 + ty * 8 + i;
            int n = n0 + tx * 4 + j;
            float v = acc[i][j];
            size_t o = (size_t)m * Nn + n;
            if (ep.mode == EP_COS) {
                float den = ep.normA[m] * ep.normB[n];
                v = v / (den == 0.0f ? 1.0f : den);
                if (ep.validf && ep.validf[n] == 0.0f) v = NEG_INF;
                C[o] = v;
            } else {
                C[o] = v;
            }
        }
    }
}

// ---------------- split-K GEMM into 128 columns: C[M,128] += A ? B[K,128] ----
// TA=0: A[M,K];  TA=1: A[K,M].  B row-major [K,128]. Output accumulated with atomics.
template <int TA>
__global__ void splitk_kernel(const float* __restrict__ A, const float* __restrict__ B,
                              float* __restrict__ C, int M, int K, int kchunk) {
    __shared__ float As[16][64 + 4];
    __shared__ float Bs[16][128 + 4];
    const int m0 = blockIdx.x * 64;
    const int kb = blockIdx.y * kchunk;
    const int tid = threadIdx.x;
    const int tx = tid & 15;   // n: 16 groups of 8
    const int ty = tid >> 4;   // m: 16 groups of 4

    float acc[4][8];
#pragma unroll
    for (int i = 0; i < 4; i++)
#pragma unroll
        for (int j = 0; j < 8; j++) acc[i][j] = 0.0f;

    for (int k0 = 0; k0 < kchunk; k0 += 16) {
        if (TA == 0) {
            int k4 = tid & 3;
            int m = tid >> 2;
            float4 v = *(const float4*)&A[(size_t)(m0 + m) * K + kb + k0 + k4 * 4];
            As[k4 * 4 + 0][m] = v.x;
            As[k4 * 4 + 1][m] = v.y;
            As[k4 * 4 + 2][m] = v.z;
            As[k4 * 4 + 3][m] = v.w;
        } else {
            int k = tid >> 4;
            int m4 = tid & 15;
            float4 v = *(const float4*)&A[(size_t)(kb + k0 + k) * M + m0 + m4 * 4];
            *(float4*)&As[k][m4 * 4] = v;
        }
#pragma unroll
        for (int l = 0; l < 2; l++) {
            int id = tid + l * 256;
            int n4 = id & 31;
            int k = id >> 5;
            float4 v = *(const float4*)&B[(size_t)(kb + k0 + k) * 128 + n4 * 4];
            *(float4*)&Bs[k][n4 * 4] = v;
        }
        __syncthreads();
#pragma unroll
        for (int k = 0; k < 16; k++) {
            float a[4], b[8];
#pragma unroll
            for (int i = 0; i < 4; i++) a[i] = As[k][ty * 4 + i];
#pragma unroll
            for (int j = 0; j < 8; j++) b[j] = Bs[k][tx * 8 + j];
#pragma unroll
            for (int i = 0; i < 4; i++)
#pragma unroll
                for (int j = 0; j < 8; j++) acc[i][j] = fmaf(a[i], b[j], acc[i][j]);
        }
        __syncthreads();
    }

#pragma unroll
    for (int i = 0; i < 4; i++)
#pragma unroll
        for (int j = 0; j < 8; j++)
            atomicAdd(&C[(size_t)(m0 + ty * 4 + i) * 128 + tx * 8 + j], acc[i][j]);
}

// ---------------- 64x64 generic GEMM (small GEMMs) ----------------
#define BM 64
#define BN 64
#define BK 32

template <int TA, int TB>
__global__ void gemm_kernel(const float* __restrict__ A, const float* __restrict__ B,
                            float* __restrict__ C, int M, int Nn, int K, EpiParams ep) {
    __shared__ float As[BK][BM + 4];
    __shared__ float Bs[BK][BN + 4];
    const int m0 = blockIdx.y * BM;
    const int n0 = blockIdx.x * BN;
    const int tid = threadIdx.x;
    const int tx = tid & 15;
    const int ty = tid >> 4;

    float acc[4][4];
#pragma unroll
    for (int i = 0; i < 4; i++)
#pragma unroll
        for (int j = 0; j < 4; j++) acc[i][j] = 0.0f;

    for (int k0 = 0; k0 < K; k0 += BK) {
        if (TA == 0) {
#pragma unroll
            for (int l = 0; l < 8; l++) {
                int id = tid + l * 256;
                int k = id & 31, m = id >> 5;
                As[k][m] = A[(size_t)(m0 + m) * K + (k0 + k)];
            }
        } else {
#pragma unroll
            for (int l = 0; l < 8; l++) {
                int id = tid + l * 256;
                int m = id & 63, k = id >> 6;
                As[k][m] = A[(size_t)(k0 + k) * M + (m0 + m)];
            }
        }
        if (TB == 0) {
#pragma unroll
            for (int l = 0; l < 8; l++) {
                int id = tid + l * 256;
                int k = id & 31, n = id >> 5;
                Bs[k][n] = B[(size_t)(n0 + n) * K + (k0 + k)];
            }
        } else {
#pragma unroll
            for (int l = 0; l < 8; l++) {
                int id = tid + l * 256;
                int n = id & 63, k = id >> 6;
                Bs[k][n] = B[(size_t)(k0 + k) * Nn + (n0 + n)];
            }
        }
        __syncthreads();
#pragma unroll
        for (int k = 0; k < BK; k++) {
            float a[4], b[4];
#pragma unroll
            for (int i = 0; i < 4; i++) a[i] = As[k][ty * 4 + i];
#pragma unroll
            for (int j = 0; j < 4; j++) b[j] = Bs[k][tx * 4 + j];
#pragma unroll
            for (int i = 0; i < 4; i++)
#pragma unroll
                for (int j = 0; j < 4; j++) acc[i][j] = fmaf(a[i], b[j], acc[i][j]);
        }
        __syncthreads();
    }

#pragma unroll
    for (int i = 0; i < 4; i++) {
#pragma unroll
        for (int j = 0; j < 4; j++) {
            int m = m0 + ty * 4 + i;
            int n = n0 + tx * 4 + j;
            float v = acc[i][j];
            size_t o = (size_t)m * Nn + n;
            switch (ep.mode) {
                case EP_NONE: C[o] = v; break;
                case EP_BIAS: C[o] = v + ep.bias[n]; break;
                case EP_BIAS_LRELU: {
                    float z = v + ep.bias[n];
                    z = z > 0.0f ? z : 0.01f * z;
                    if (ep.accum) C[o] += z; else C[o] = z;
                    break;
                }
                case EP_COS: {
                    float den = ep.normA[m] * ep.normB[n];
                    v = v / (den == 0.0f ? 1.0f : den);
                    if (ep.validf && ep.validf[n] == 0.0f) v = NEG_INF;
                    C[o] = v;
                    break;
                }
                case EP_RESID: C[o] = ep.resid[o] - (v + ep.bias[n]); break;
            }
        }
    }
}

// ---------------- small kernels ----------------
__global__ void colsum_cm_kernel(const float* __restrict__ cm, const float* __restrict__ mv,
                                 float* __restrict__ colsum) {
    int b = blockIdx.x;      // 32 blocks x 128 rows
    int t = threadIdx.x;     // 256
    float s0 = 0.0f, s1 = 0.0f;
    for (int rr = 0; rr < 128; rr++) {
        int r = b * 128 + rr;
        float m = mv[r];
        s0 += cm[(size_t)r * CC + t] * m;
        s1 += cm[(size_t)r * CC + 256 + t] * m;
    }
    atomicAdd(&colsum[t], s0);
    atomicAdd(&colsum[t + 256], s1);
}

__global__ void s2c_kernel(const float* __restrict__ cm, const float* __restrict__ mv,
                           const float* __restrict__ colsum, float* __restrict__ out) {
    int idx = blockIdx.x * blockDim.x + threadIdx.x;
    if (idx >= NN * CC) return;
    int i = idx / CC;
    int c = idx - i * CC;
    float m = cm[idx];
    out[idx] = (m * mv[i]) / (colsum[c] * m + 1.0f);
}

__global__ void rowflag_kernel(const float* __restrict__ X, float* __restrict__ validf) {
    int m = blockIdx.x;
    int t = threadIdx.x;  // 128
    __shared__ float sh[128];
    sh[t] = X[(size_t)m * HH + t];
    __syncthreads();
    for (int o = 64; o > 0; o >>= 1) {
        if (t < o) sh[t] += sh[t + o];
        __syncthreads();
    }
    if (t == 0) validf[m] = (sh[0] != 0.0f) ? 1.0f : 0.0f;
}

__global__ void rownorm_kernel(const float* __restrict__ X, float* __restrict__ norm,
                               float* __restrict__ diag) {
    int m = blockIdx.x;
    int t = threadIdx.x;  // 128
    float v = X[(size_t)m * HH + t];
    __shared__ float sh[128];
    sh[t] = v * v;
    __syncthreads();
    for (int o = 64; o > 0; o >>= 1) {
        if (t < o) sh[t] += sh[t + o];
        __syncthreads();
    }
    if (t == 0) {
        float ss = sh[0];
        float n = sqrtf(ss);
        norm[m] = n;
        if (diag) {
            float den = n * n;
            diag[m] = (den == 0.0f) ? 0.0f : ss / den;
        }
    }
}

__global__ void scale_rows_kernel(float* __restrict__ X, const float* __restrict__ s, int total) {
    int idx = blockIdx.x * blockDim.x + threadIdx.x;
    if (idx >= total) return;
    X[idx] *= s[idx >> 7];
}

// register-resident softmax: 1 read + 1 write. L must be multiple of 256, L/256 <= 16.
__global__ void softmax_kernel(float* __restrict__ buf, int L) {
    int r = blockIdx.x;
    float* row = buf + (size_t)r * L;
    int t = threadIdx.x;  // 256
    int V = L >> 8;
    float v[16];
    float mx = NEG_INF;
    for (int u = 0; u < V; u++) {
        v[u] = row[t + (u << 8)];
        mx = fmaxf(mx, v[u]);
    }
    __shared__ float sh[256];
    sh[t] = mx;
    __syncthreads();
    for (int o = 128; o > 0; o >>= 1) {
        if (t < o) sh[t] = fmaxf(sh[t], sh[t + o]);
        __syncthreads();
    }
    mx = sh[0];
    __syncthreads();
    float s = 0.0f;
    for (int u = 0; u < V; u++) {
        v[u] = expf(v[u] - mx);
        s += v[u];
    }
    sh[t] = s;
    __syncthreads();
    for (int o = 128; o > 0; o >>= 1) {
        if (t < o) sh[t] += sh[t + o];
        __syncthreads();
    }
    float inv = 1.0f / sh[0];
    for (int u = 0; u < V; u++) row[t + (u << 8)] = v[u] * inv;
}

__global__ void top3_scatter_kernel(const float* __restrict__ big, const float* __restrict__ h,
                                    float* __restrict__ hidden2, float* __restrict__ colsum2) {
    int i = blockIdx.x;
    int t = threadIdx.x;  // 128
    const float* row = big + (size_t)i * NN;
    float v0 = NEG_INF, v1 = NEG_INF, v2 = NEG_INF;
    int i0 = 0, i1 = 0, i2 = 0;
    for (int j = t; j < NN; j += 128) {
        float v = (j == i) ? 0.0f : row[j];
        if (v > v0) { v2 = v1; i2 = i1; v1 = v0; i1 = i0; v0 = v; i0 = j; }
        else if (v > v1) { v2 = v1; i2 = i1; v1 = v; i1 = j; }
        else if (v > v2) { v2 = v; i2 = j; }
    }
    __shared__ float sv[384];
    __shared__ int si[384];
    __shared__ float bv[KTOP];
    __shared__ int bi[KTOP];
    sv[t] = v0; sv[128 + t] = v1; sv[256 + t] = v2;
    si[t] = i0; si[128 + t] = i1; si[256 + t] = i2;
    __syncthreads();
    if (t == 0) {
        for (int k = 0; k < KTOP; k++) {
            float best = NEG_INF;
            int bq = 0;
            for (int q = 0; q < 384; q++)
                if (sv[q] > best) { best = sv[q]; bq = q; }
            bv[k] = best;
            bi[k] = si[bq];
            sv[bq] = NEG_INF;
        }
    }
    __syncthreads();
    float hv = h[(size_t)i * HH + t];
#pragma unroll
    for (int k = 0; k < KTOP; k++) {
        int j = bi[k];
        float v = bv[k];
        atomicAdd(&hidden2[(size_t)j * HH + t], v * hv);
        if (t == 0) atomicAdd(&colsum2[j], v);
    }
}

__global__ void zero_kernel(float* __restrict__ a, int n) {
    int i = blockIdx.x * blockDim.x + threadIdx.x;
    if (i < n) a[i] = 0.0f;
}

__global__ void diag_valid_kernel(const float* __restrict__ colsum2, const float* __restrict__ diag,
                                  const float* __restrict__ h, float* __restrict__ hidden2,
                                  float* __restrict__ valid2f, float* __restrict__ norm2) {
    int j = blockIdx.x;
    int t = threadIdx.x;  // 128
    float dterm = (colsum2[j] != 0.0f) ? diag[j] : 0.0f;
    float v = hidden2[(size_t)j * HH + t] + dterm * h[(size_t)j * HH + t];
    __shared__ float shs[128];
    __shared__ float shq[128];
    shs[t] = v;
    shq[t] = v * v;
    __syncthreads();
    for (int o = 64; o > 0; o >>= 1) {
        if (t < o) { shs[t] += shs[t + o]; shq[t] += shq[t + o]; }
        __syncthreads();
    }
    float valid = (shs[0] != 0.0f) ? 1.0f : 0.0f;
    hidden2[(size_t)j * HH + t] = v * valid;
    if (t == 0) {
        valid2f[j] = valid;
        norm2[j] = valid * sqrtf(shq[0]);
    }
}

__global__ void final_kernel(const float* __restrict__ outsum, const float* __restrict__ Wout,
                             const float* __restrict__ bout, float* __restrict__ y) {
    int i = blockIdx.x;
    int t = threadIdx.x;  // 128
    __shared__ float sh[128];
    sh[t] = outsum[(size_t)i * HH + t] * Wout[t];
    __syncthreads();
    for (int o = 64; o > 0; o >>= 1) {
        if (t < o) sh[t] += sh[t + o];
        __syncthreads();
    }
    if (t == 0) y[i] = sh[0] + bout[0];
}

// ---------------- host orchestration ----------------
static EpiParams ep_make(int mode) {
    EpiParams e;
    e.mode = mode; e.accum = 0;
    e.bias = nullptr; e.normA = nullptr; e.normB = nullptr;
    e.validf = nullptr; e.resid = nullptr;
    return e;
}

static void launch_gemm64(int TA, int TB, const float* A, const float* B, float* C,
                          int M, int Nn, int K, const EpiParams& ep) {
    dim3 grid(Nn / BN, M / BM), block(256);
    if (TA == 0 && TB == 0) gemm_kernel<0, 0><<<grid, block>>>(A, B, C, M, Nn, K, ep);
    else if (TA == 0 && TB == 1) gemm_kernel<0, 1><<<grid, block>>>(A, B, C, M, Nn, K, ep);
    else if (TA == 1 && TB == 1) gemm_kernel<1, 1><<<grid, block>>>(A, B, C, M, Nn, K, ep);
    else gemm_kernel<1, 0><<<grid, block>>>(A, B, C, M, Nn, K, ep);
}

static void launch_gemm128(const float* A, const float* B, float* C,
                           int M, int Nn, int K, const EpiParams& ep) {
    dim3 grid(Nn / 64, M / 128), block(256);
    gemm128_kernel<<<grid, block>>>(A, B, C, M, Nn, K, ep);
}

#define SYM(p, s) do { void* _tmp; cudaGetSymbolAddress(&_tmp, s); p = (float*)_tmp; } while (0)

extern "C" void kernel_launch(void* const* d_in, const int* in_sizes, int n_in,
                              void* d_out, int out_size) {
    const float* x = (const float*)d_in[0];
    const float* cm = (const float*)d_in[1];
    const float* mv = (const float*)d_in[2];
    const float* W_ps = (const float*)d_in[3];
    const float* b_ps = (const float*)d_in[4];
    const float* W_psf = (const float*)d_in[5];
    const float* b_psf = (const float*)d_in[6];
    const float* W_psb = (const float*)d_in[7];
    const float* b_psb = (const float*)d_in[8];
    const float* W_hs = (const float*)d_in[9];
    const float* b_hs = (const float*)d_in[10];
    const float* W_hsf = (const float*)d_in[11];
    const float* b_hsf = (const float*)d_in[12];
    const float* W_hsb = (const float*)d_in[13];
    const float* b_hsb = (const float*)d_in[14];
    const float* W_in = (const float*)d_in[15];
    const float* b_in = (const float*)d_in[16];
    const float* W_out = (const float*)d_in[17];
    const float* b_out = (const float*)d_in[18];
    float* y = (float*)d_out;

    float *p_big, *p_nc, *p_hidden1, *p_hiddenB, *p_tmp, *p_pshared, *p_h, *p_hidden2,
        *p_hshared, *p_indiv, *p_outsum, *p_colsum, *p_valid1, *p_normx, *p_normB, *p_normh,
        *p_diag, *p_norm2, *p_valid2, *p_colsum2;
    SYM(p_big, g_big); SYM(p_nc, g_nc); SYM(p_hidden1, g_hidden1); SYM(p_hiddenB, g_hiddenB);
    SYM(p_tmp, g_tmp); SYM(p_pshared, g_pshared); SYM(p_h, g_h); SYM(p_hidden2, g_hidden2);
    SYM(p_hshared, g_hshared); SYM(p_indiv, g_indiv); SYM(p_outsum, g_outsum);
    SYM(p_colsum, g_colsum); SYM(p_valid1, g_valid1); SYM(p_normx, g_normx);
    SYM(p_normB, g_normB); SYM(p_normh, g_normh); SYM(p_diag, g_diag); SYM(p_norm2, g_norm2);
    SYM(p_valid2, g_valid2); SYM(p_colsum2, g_colsum2);

    // zeros for atomic accumulators
    zero_kernel<<<(CC + 255) / 256, 256>>>(p_colsum, CC);
    zero_kernel<<<(CC * HH + 255) / 256, 256>>>(p_hidden1, CC * HH);
    zero_kernel<<<(CC * HH + 255) / 256, 256>>>(p_hiddenB, CC * HH);
    zero_kernel<<<(NN * HH + 255) / 256, 256>>>(p_hidden2, NN * HH);
    zero_kernel<<<(NN + 255) / 256, 256>>>(p_colsum2, NN);

    rownorm_kernel<<<NN, 128>>>(x, p_normx, nullptr);

    // ---- ps branch ----
    colsum_cm_kernel<<<32, 256>>>(cm, mv, p_colsum);
    s2c_kernel<<<(NN * CC + 255) / 256, 256>>>(cm, mv, p_colsum, p_nc);
    // hidden1 = s2c^T @ x  [C,H], split-K 16
    {
        dim3 grid(CC / 64, 16), block(256);
        splitk_kernel<1><<<grid, block>>>(p_nc, x, p_hidden1, CC, NN, NN / 16);
    }
    rowflag_kernel<<<CC, 128>>>(p_hidden1, p_valid1);
    // logitsT = hidden1 @ x^T  [C,N]
    launch_gemm128(p_hidden1, x, p_nc, CC, NN, HH, ep_make(EP_NONE));
    softmax_kernel<<<CC, 256>>>(p_nc, NN);
    // hiddenB = s2c2^T @ x  [C,H], split-K 16
    {
        dim3 grid(CC / 64, 16), block(256);
        splitk_kernel<0><<<grid, block>>>(p_nc, x, p_hiddenB, CC, NN, NN / 16);
    }
    scale_rows_kernel<<<(CC * HH + 255) / 256, 256>>>(p_hiddenB, p_valid1, CC * HH);
    rownorm_kernel<<<CC, 128>>>(p_hiddenB, p_normB, nullptr);
    // cos(x, hiddenB) -> [N,C]
    {
        EpiParams e = ep_make(EP_COS);
        e.normA = p_normx; e.normB = p_normB; e.validf = p_valid1;
        launch_gemm128(x, p_hiddenB, p_nc, NN, CC, HH, e);
    }
    softmax_kernel<<<NN, 256>>>(p_nc, CC);
    // tmp = c2s @ hiddenB  [N,H]
    launch_gemm64(0, 1, p_nc, p_hiddenB, p_tmp, NN, HH, CC, ep_make(EP_NONE));
    {
        EpiParams e = ep_make(EP_BIAS);
        e.bias = b_ps;
        launch_gemm64(0, 0, p_tmp, W_ps, p_pshared, NN, HH, HH, e);
    }
    {
        EpiParams e = ep_make(EP_RESID);
        e.bias = b_psb; e.resid = x;
        launch_gemm64(0, 0, p_pshared, W_psb, p_h, NN, HH, HH, e);
    }
    {
        EpiParams e = ep_make(EP_BIAS_LRELU);
        e.bias = b_psf; e.accum = 0;
        launch_gemm64(0, 0, p_pshared, W_psf, p_outsum, NN, HH, HH, e);
    }

    // ---- hs branch ----
    rownorm_kernel<<<NN, 128>>>(p_h, p_normh, p_diag);
    {
        EpiParams e = ep_make(EP_COS);
        e.normA = p_normh; e.normB = p_normh;
        launch_gemm128(p_h, p_h, p_big, NN, NN, HH, e);
    }
    top3_scatter_kernel<<<NN, 128>>>(p_big, p_h, p_hidden2, p_colsum2);
    diag_valid_kernel<<<NN, 128>>>(p_colsum2, p_diag, p_h, p_hidden2, p_valid2, p_norm2);
    {
        EpiParams e = ep_make(EP_COS);
        e.normA = p_normh; e.normB = p_norm2; e.validf = p_valid2;
        launch_gemm128(p_h, p_hidden2, p_big, NN, NN, HH, e);
    }
    softmax_kernel<<<NN, 256>>>(p_big, NN);
    // tmp = hc2s @ hidden2  [N,H], split-K 4
    zero_kernel<<<(NN * HH + 255) / 256, 256>>>(p_tmp, NN * HH);
    {
        dim3 grid(NN / 64, 4), block(256);
        splitk_kernel<0><<<grid, block>>>(p_big, p_hidden2, p_tmp, NN, NN, NN / 4);
    }
    {
        EpiParams e = ep_make(EP_BIAS);
        e.bias = b_hs;
        launch_gemm64(0, 0, p_tmp, W_hs, p_hshared, NN, HH, HH, e);
    }
    {
        EpiParams e = ep_make(EP_RESID);
        e.bias = b_hsb; e.resid = p_h;
        launch_gemm64(0, 0, p_hshared, W_hsb, p_indiv, NN, HH, HH, e);
    }
    {
        EpiParams e = ep_make(EP_BIAS_LRELU);
        e.bias = b_hsf; e.accum = 1;
        launch_gemm64(0, 0, p_hshared, W_hsf, p_outsum, NN, HH, HH, e);
    }
    {
        EpiParams e = ep_make(EP_BIAS_LRELU);
        e.bias = b_in; e.accum = 1;
        launch_gemm64(0, 0, p_indiv, W_in, p_outsum, NN, HH, HH, e);
    }

    final_kernel<<<NN, 128>>>(p_outsum, W_out, b_out, y);
}

// round 4
// speedup vs baseline: 2.0471x; 1.2267x over previous
#include <cuda_runtime.h>
#include <cuda_bf16.h>
#include <math.h>
#include <stdint.h>

#define NN 4096
#define CC 512
#define HH 128
#define KTOP 3

#define NEG_INF (__int_as_float(0xff800000))

// ---------------- static scratch ----------------
__device__ float g_big[(size_t)NN * NN];
__device__ float g_nc[(size_t)NN * CC];
__device__ float g_hidden1[CC * HH];
__device__ float g_hiddenB[CC * HH];
__device__ float g_tmp[NN * HH];
__device__ float g_pshared[NN * HH];
__device__ float g_h[NN * HH];
__device__ float g_hidden2[NN * HH];
__device__ float g_hshared[NN * HH];
__device__ float g_indiv[NN * HH];
__device__ float g_outsum[NN * HH];
__device__ float g_colsum[CC];
__device__ float g_valid1[CC];
__device__ float g_normx[NN];
__device__ float g_normB[CC];
__device__ float g_normh[NN];
__device__ float g_diag[NN];
__device__ float g_norm2[NN];
__device__ float g_valid2[NN];
__device__ float g_colsum2[NN];

// bf16 split-3 buffers
__device__ __nv_bfloat16 g_xA3[(size_t)NN * 3 * HH];
__device__ __nv_bfloat16 g_xB3[(size_t)NN * 3 * HH];
__device__ __nv_bfloat16 g_hA3[(size_t)NN * 3 * HH];
__device__ __nv_bfloat16 g_hB3[(size_t)NN * 3 * HH];
__device__ __nv_bfloat16 g_h1A3[(size_t)CC * 3 * HH];
__device__ __nv_bfloat16 g_hBB3[(size_t)CC * 3 * HH];
__device__ __nv_bfloat16 g_hBT3[(size_t)HH * 3 * CC];
__device__ __nv_bfloat16 g_h2B3[(size_t)NN * 3 * HH];
__device__ __nv_bfloat16 g_h2T3[(size_t)HH * 3 * NN];
__device__ __nv_bfloat16 g_c2sA3[(size_t)NN * 3 * CC];
__device__ __nv_bfloat16 g_probsA3[(size_t)NN * 3 * NN];

enum { EP_NONE = 0, EP_BIAS = 1, EP_BIAS_LRELU = 2, EP_COS = 3, EP_RESID = 5, EP_ATOM = 6 };

struct EpiParams {
    int mode;
    int accum;
    const float* bias;
    const float* normA;
    const float* normB;
    const float* validf;
    const float* resid;
};

// ---------------- mma.sync bf16 GEMM: C[M,Nn] = A[M,Ktot] @ B[Nn,Ktot]^T ----------------
// 128x128 tile, BK=32, 8 warps (2x4), warp tile 64x32, m16n8k16 fragments.
// Smem rows padded to 80 bytes (conflict-free for the 16816 access pattern).

#define SMEM_ROW 80

__device__ __forceinline__ void mma16816(float* c, const uint32_t* a, const uint32_t* b) {
    asm volatile(
        "mma.sync.aligned.m16n8k16.row.col.f32.bf16.bf16.f32 "
        "{%0,%1,%2,%3}, {%4,%5,%6,%7}, {%8,%9}, {%0,%1,%2,%3};"
        : "+f"(c[0]), "+f"(c[1]), "+f"(c[2]), "+f"(c[3])
        : "r"(a[0]), "r"(a[1]), "r"(a[2]), "r"(a[3]), "r"(b[0]), "r"(b[1]));
}

__device__ __forceinline__ void cp_async16(uint32_t smem_addr, const void* gptr) {
    asm volatile("cp.async.cg.shared.global [%0], [%1], 16;" :: "r"(smem_addr), "l"(gptr));
}

__global__ void __launch_bounds__(256)
mma_gemm(const __nv_bfloat16* __restrict__ A, const __nv_bfloat16* __restrict__ B,
         float* __restrict__ C, int M, int Nn, int Ktot, int kchunk, EpiParams ep) {
    __shared__ __align__(16) char As_[2][128 * SMEM_ROW];
    __shared__ __align__(16) char Bs_[2][128 * SMEM_ROW];

    const int tid = threadIdx.x;
    const int lane = tid & 31;
    const int wid = tid >> 5;
    const int warp_m = (wid >> 2) * 64;
    const int warp_n = (wid & 3) * 32;
    const int m0 = blockIdx.y * 128;
    const int n0 = blockIdx.x * 128;
    const int kbase = blockIdx.z * kchunk;
    const int niter = kchunk >> 5;

    const char* Ag = (const char*)(A + (size_t)m0 * Ktot + kbase);
    const char* Bg = (const char*)(B + (size_t)n0 * Ktot + kbase);
    const size_t rowb = (size_t)Ktot * 2;

    uint32_t asb = (uint32_t)__cvta_generic_to_shared(&As_[0][0]);
    uint32_t bsb = (uint32_t)__cvta_generic_to_shared(&Bs_[0][0]);

    float acc[4][4][4];
#pragma unroll
    for (int i = 0; i < 4; i++)
#pragma unroll
        for (int j = 0; j < 4; j++)
#pragma unroll
            for (int q = 0; q < 4; q++) acc[i][j][q] = 0.0f;

    // loader: 512 chunk tasks (128 rows x 4 x 16B), 2 per thread
    const int lm0 = tid >> 2;       // rows tid>>2 and +64
    const int lc = tid & 3;

#define LOAD_TILE(s, it) do { \
    size_t goff = (size_t)(it) * 64 + lc * 16; \
    uint32_t soff = (uint32_t)((s) * 128 * SMEM_ROW + lc * 16); \
    cp_async16(asb + soff + lm0 * SMEM_ROW, Ag + (size_t)lm0 * rowb + goff); \
    cp_async16(asb + soff + (lm0 + 64) * SMEM_ROW, Ag + (size_t)(lm0 + 64) * rowb + goff); \
    cp_async16(bsb + soff + lm0 * SMEM_ROW, Bg + (size_t)lm0 * rowb + goff); \
    cp_async16(bsb + soff + (lm0 + 64) * SMEM_ROW, Bg + (size_t)(lm0 + 64) * rowb + goff); \
    asm volatile("cp.async.commit_group;"); \
} while (0)

    LOAD_TILE(0, 0);

    for (int it = 0; it < niter; it++) {
        int s = it & 1;
        if (it + 1 < niter) {
            LOAD_TILE(s ^ 1, it + 1);
            asm volatile("cp.async.wait_group 1;");
        } else {
            asm volatile("cp.async.wait_group 0;");
        }
        __syncthreads();

        const char* Asb = As_[s];
        const char* Bsb = Bs_[s];
#pragma unroll
        for (int ks = 0; ks < 32; ks += 16) {
            uint32_t a[4][4], b[4][2];
            int cb2 = (ks + (lane & 3) * 2) * 2;  // byte offset of k pos
#pragma unroll
            for (int mi = 0; mi < 4; mi++) {
                int r = warp_m + mi * 16 + (lane >> 2);
                a[mi][0] = *(const uint32_t*)(Asb + r * SMEM_ROW + cb2);
                a[mi][1] = *(const uint32_t*)(Asb + (r + 8) * SMEM_ROW + cb2);
                a[mi][2] = *(const uint32_t*)(Asb + r * SMEM_ROW + cb2 + 16);
                a[mi][3] = *(const uint32_t*)(Asb + (r + 8) * SMEM_ROW + cb2 + 16);
            }
#pragma unroll
            for (int ni = 0; ni < 4; ni++) {
                int rn = warp_n + ni * 8 + (lane >> 2);
                b[ni][0] = *(const uint32_t*)(Bsb + rn * SMEM_ROW + cb2);
                b[ni][1] = *(const uint32_t*)(Bsb + rn * SMEM_ROW + cb2 + 16);
            }
#pragma unroll
            for (int mi = 0; mi < 4; mi++)
#pragma unroll
                for (int ni = 0; ni < 4; ni++) mma16816(acc[mi][ni], a[mi], b[ni]);
        }
        __syncthreads();
    }

    // epilogue
#pragma unroll
    for (int mi = 0; mi < 4; mi++) {
        int r0 = m0 + warp_m + mi * 16 + (lane >> 2);
#pragma unroll
        for (int ni = 0; ni < 4; ni++) {
            int c = n0 + warp_n + ni * 8 + (lane & 3) * 2;
#pragma unroll
            for (int half = 0; half < 2; half++) {
                int m = r0 + half * 8;
                float v0 = acc[mi][ni][half * 2];
                float v1 = acc[mi][ni][half * 2 + 1];
                size_t o = (size_t)m * Nn + c;
                if (ep.mode == EP_COS) {
                    float na = ep.normA[m];
                    float d0 = na * ep.normB[c];
                    float d1 = na * ep.normB[c + 1];
                    v0 = v0 / (d0 == 0.0f ? 1.0f : d0);
                    v1 = v1 / (d1 == 0.0f ? 1.0f : d1);
                    if (ep.validf) {
                        if (ep.validf[c] == 0.0f) v0 = NEG_INF;
                        if (ep.validf[c + 1] == 0.0f) v1 = NEG_INF;
                    }
                    *(float2*)&C[o] = make_float2(v0, v1);
                } else if (ep.mode == EP_ATOM) {
                    atomicAdd(&C[o], v0);
                    atomicAdd(&C[o + 1], v1);
                } else {
                    *(float2*)&C[o] = make_float2(v0, v1);
                }
            }
        }
    }
}

// ---------------- split-3 conversion kernels ----------------
__global__ void split3_kernel(const float* __restrict__ X, __nv_bfloat16* __restrict__ Y,
                              int R, int K, int patA) {
    size_t idx = (size_t)blockIdx.x * blockDim.x + threadIdx.x;
    if (idx >= (size_t)R * K) return;
    int r = (int)(idx / K);
    int k = (int)(idx - (size_t)r * K);
    float v = X[idx];
    __nv_bfloat16 h = __float2bfloat16(v);
    __nv_bfloat16 l = __float2bfloat16(v - __bfloat162float(h));
    size_t base = (size_t)r * 3 * K + k;
    Y[base] = h;
    Y[base + K] = patA ? h : l;
    Y[base + 2 * K] = patA ? l : h;
}

// X [K, 128] fp32 -> Y [128, 3K] bf16, B-pattern [h,l,h]
__global__ void transpose_split3_kernel(const float* __restrict__ X,
                                        __nv_bfloat16* __restrict__ Y, int K) {
    __shared__ float tile[32][33];
    int k0 = blockIdx.x * 32, h0 = blockIdx.y * 32;
    int tx = threadIdx.x, ty = threadIdx.y;
    for (int r = ty; r < 32; r += 8)
        tile[r][tx] = X[(size_t)(k0 + r) * HH + h0 + tx];
    __syncthreads();
    for (int r = ty; r < 32; r += 8) {
        int hcol = h0 + r;
        int k = k0 + tx;
        float v = tile[tx][r];
        __nv_bfloat16 h = __float2bfloat16(v);
        __nv_bfloat16 l = __float2bfloat16(v - __bfloat162float(h));
        size_t base = (size_t)hcol * 3 * K + k;
        Y[base] = h;
        Y[base + K] = l;
        Y[base + 2 * K] = h;
    }
}

// ---------------- fp32 split-K GEMM into 128 cols ----------------
template <int TA>
__global__ void splitk_kernel(const float* __restrict__ A, const float* __restrict__ B,
                              float* __restrict__ C, int M, int K, int kchunk) {
    __shared__ float As[16][64 + 4];
    __shared__ float Bs[16][128 + 4];
    const int m0 = blockIdx.x * 64;
    const int kb = blockIdx.y * kchunk;
    const int tid = threadIdx.x;
    const int tx = tid & 15;
    const int ty = tid >> 4;

    float acc[4][8];
#pragma unroll
    for (int i = 0; i < 4; i++)
#pragma unroll
        for (int j = 0; j < 8; j++) acc[i][j] = 0.0f;

    for (int k0 = 0; k0 < kchunk; k0 += 16) {
        if (TA == 0) {
            int k4 = tid & 3;
            int m = tid >> 2;
            float4 v = *(const float4*)&A[(size_t)(m0 + m) * K + kb + k0 + k4 * 4];
            As[k4 * 4 + 0][m] = v.x;
            As[k4 * 4 + 1][m] = v.y;
            As[k4 * 4 + 2][m] = v.z;
            As[k4 * 4 + 3][m] = v.w;
        } else {
            int k = tid >> 4;
            int m4 = tid & 15;
            float4 v = *(const float4*)&A[(size_t)(kb + k0 + k) * M + m0 + m4 * 4];
            *(float4*)&As[k][m4 * 4] = v;
        }
#pragma unroll
        for (int l = 0; l < 2; l++) {
            int id = tid + l * 256;
            int n4 = id & 31;
            int k = id >> 5;
            float4 v = *(const float4*)&B[(size_t)(kb + k0 + k) * 128 + n4 * 4];
            *(float4*)&Bs[k][n4 * 4] = v;
        }
        __syncthreads();
#pragma unroll
        for (int k = 0; k < 16; k++) {
            float a[4], b[8];
#pragma unroll
            for (int i = 0; i < 4; i++) a[i] = As[k][ty * 4 + i];
#pragma unroll
            for (int j = 0; j < 8; j++) b[j] = Bs[k][tx * 8 + j];
#pragma unroll
            for (int i = 0; i < 4; i++)
#pragma unroll
                for (int j = 0; j < 8; j++) acc[i][j] = fmaf(a[i], b[j], acc[i][j]);
        }
        __syncthreads();
    }
#pragma unroll
    for (int i = 0; i < 4; i++)
#pragma unroll
        for (int j = 0; j < 8; j++)
            atomicAdd(&C[(size_t)(m0 + ty * 4 + i) * 128 + tx * 8 + j], acc[i][j]);
}

// ---------------- 64x64 fp32 GEMM for HHxHH weight layers ----------------
#define BM 64
#define BN 64
#define BK 32

template <int TA, int TB>
__global__ void gemm_kernel(const float* __restrict__ A, const float* __restrict__ B,
                            float* __restrict__ C, int M, int Nn, int K, EpiParams ep) {
    __shared__ float As[BK][BM + 4];
    __shared__ float Bs[BK][BN + 4];
    const int m0 = blockIdx.y * BM;
    const int n0 = blockIdx.x * BN;
    const int tid = threadIdx.x;
    const int tx = tid & 15;
    const int ty = tid >> 4;

    float acc[4][4];
#pragma unroll
    for (int i = 0; i < 4; i++)
#pragma unroll
        for (int j = 0; j < 4; j++) acc[i][j] = 0.0f;

    for (int k0 = 0; k0 < K; k0 += BK) {
        if (TA == 0) {
#pragma unroll
            for (int l = 0; l < 8; l++) {
                int id = tid + l * 256;
                int k = id & 31, m = id >> 5;
                As[k][m] = A[(size_t)(m0 + m) * K + (k0 + k)];
            }
        } else {
#pragma unroll
            for (int l = 0; l < 8; l++) {
                int id = tid + l * 256;
                int m = id & 63, k = id >> 6;
                As[k][m] = A[(size_t)(k0 + k) * M + (m0 + m)];
            }
        }
        if (TB == 0) {
#pragma unroll
            for (int l = 0; l < 8; l++) {
                int id = tid + l * 256;
                int k = id & 31, n = id >> 5;
                Bs[k][n] = B[(size_t)(n0 + n) * K + (k0 + k)];
            }
        } else {
#pragma unroll
            for (int l = 0; l < 8; l++) {
                int id = tid + l * 256;
                int n = id & 63, k = id >> 6;
                Bs[k][n] = B[(size_t)(k0 + k) * Nn + (n0 + n)];
            }
        }
        __syncthreads();
#pragma unroll
        for (int k = 0; k < BK; k++) {
            float a[4], b[4];
#pragma unroll
            for (int i = 0; i < 4; i++) a[i] = As[k][ty * 4 + i];
#pragma unroll
            for (int j = 0; j < 4; j++) b[j] = Bs[k][tx * 4 + j];
#pragma unroll
            for (int i = 0; i < 4; i++)
#pragma unroll
                for (int j = 0; j < 4; j++) acc[i][j] = fmaf(a[i], b[j], acc[i][j]);
        }
        __syncthreads();
    }

#pragma unroll
    for (int i = 0; i < 4; i++) {
#pragma unroll
        for (int j = 0; j < 4; j++) {
            int m = m0 + ty * 4 + i;
            int n = n0 + tx * 4 + j;
            float v = acc[i][j];
            size_t o = (size_t)m * Nn + n;
            switch (ep.mode) {
                case EP_NONE: C[o] = v; break;
                case EP_BIAS: C[o] = v + ep.bias[n]; break;
                case EP_BIAS_LRELU: {
                    float z = v + ep.bias[n];
                    z = z > 0.0f ? z : 0.01f * z;
                    if (ep.accum) C[o] += z; else C[o] = z;
                    break;
                }
                case EP_RESID: C[o] = ep.resid[o] - (v + ep.bias[n]); break;
            }
        }
    }
}

// ---------------- small kernels ----------------
__global__ void colsum_cm_kernel(const float* __restrict__ cm, const float* __restrict__ mv,
                                 float* __restrict__ colsum) {
    int b = blockIdx.x;
    int t = threadIdx.x;
    float s0 = 0.0f, s1 = 0.0f;
    for (int rr = 0; rr < 128; rr++) {
        int r = b * 128 + rr;
        float m = mv[r];
        s0 += cm[(size_t)r * CC + t] * m;
        s1 += cm[(size_t)r * CC + 256 + t] * m;
    }
    atomicAdd(&colsum[t], s0);
    atomicAdd(&colsum[t + 256], s1);
}

__global__ void s2c_kernel(const float* __restrict__ cm, const float* __restrict__ mv,
                           const float* __restrict__ colsum, float* __restrict__ out) {
    int idx = blockIdx.x * blockDim.x + threadIdx.x;
    if (idx >= NN * CC) return;
    int i = idx / CC;
    int c = idx - i * CC;
    float m = cm[idx];
    out[idx] = (m * mv[i]) / (colsum[c] * m + 1.0f);
}

__global__ void rowflag_kernel(const float* __restrict__ X, float* __restrict__ validf) {
    int m = blockIdx.x;
    int t = threadIdx.x;
    __shared__ float sh[128];
    sh[t] = X[(size_t)m * HH + t];
    __syncthreads();
    for (int o = 64; o > 0; o >>= 1) {
        if (t < o) sh[t] += sh[t + o];
        __syncthreads();
    }
    if (t == 0) validf[m] = (sh[0] != 0.0f) ? 1.0f : 0.0f;
}

__global__ void rownorm_kernel(const float* __restrict__ X, float* __restrict__ norm,
                               float* __restrict__ diag) {
    int m = blockIdx.x;
    int t = threadIdx.x;
    float v = X[(size_t)m * HH + t];
    __shared__ float sh[128];
    sh[t] = v * v;
    __syncthreads();
    for (int o = 64; o > 0; o >>= 1) {
        if (t < o) sh[t] += sh[t + o];
        __syncthreads();
    }
    if (t == 0) {
        float ss = sh[0];
        float n = sqrtf(ss);
        norm[m] = n;
        if (diag) {
            float den = n * n;
            diag[m] = (den == 0.0f) ? 0.0f : ss / den;
        }
    }
}

__global__ void scale_rows_kernel(float* __restrict__ X, const float* __restrict__ s, int total) {
    int idx = blockIdx.x * blockDim.x + threadIdx.x;
    if (idx >= total) return;
    X[idx] *= s[idx >> 7];
}

__global__ void softmax_kernel(float* __restrict__ buf, int L) {
    int r = blockIdx.x;
    float* row = buf + (size_t)r * L;
    int t = threadIdx.x;
    int V = L >> 8;
    float v[16];
    float mx = NEG_INF;
    for (int u = 0; u < V; u++) {
        v[u] = row[t + (u << 8)];
        mx = fmaxf(mx, v[u]);
    }
    __shared__ float sh[256];
    sh[t] = mx;
    __syncthreads();
    for (int o = 128; o > 0; o >>= 1) {
        if (t < o) sh[t] = fmaxf(sh[t], sh[t + o]);
        __syncthreads();
    }
    mx = sh[0];
    __syncthreads();
    float s = 0.0f;
    for (int u = 0; u < V; u++) {
        v[u] = expf(v[u] - mx);
        s += v[u];
    }
    sh[t] = s;
    __syncthreads();
    for (int o = 128; o > 0; o >>= 1) {
        if (t < o) sh[t] += sh[t + o];
        __syncthreads();
    }
    float inv = 1.0f / sh[0];
    for (int u = 0; u < V; u++) row[t + (u << 8)] = v[u] * inv;
}

__global__ void top3_scatter_kernel(const float* __restrict__ big, const float* __restrict__ h,
                                    float* __restrict__ hidden2, float* __restrict__ colsum2) {
    int i = blockIdx.x;
    int t = threadIdx.x;
    const float* row = big + (size_t)i * NN;
    float v0 = NEG_INF, v1 = NEG_INF, v2 = NEG_INF;
    int i0 = 0, i1 = 0, i2 = 0;
    for (int j = t; j < NN; j += 128) {
        float v = (j == i) ? 0.0f : row[j];
        if (v > v0) { v2 = v1; i2 = i1; v1 = v0; i1 = i0; v0 = v; i0 = j; }
        else if (v > v1) { v2 = v1; i2 = i1; v1 = v; i1 = j; }
        else if (v > v2) { v2 = v; i2 = j; }
    }
    __shared__ float sv[384];
    __shared__ int si[384];
    __shared__ float bv[KTOP];
    __shared__ int bi[KTOP];
    sv[t] = v0; sv[128 + t] = v1; sv[256 + t] = v2;
    si[t] = i0; si[128 + t] = i1; si[256 + t] = i2;
    __syncthreads();
    if (t == 0) {
        for (int k = 0; k < KTOP; k++) {
            float best = NEG_INF;
            int bq = 0;
            for (int q = 0; q < 384; q++)
                if (sv[q] > best) { best = sv[q]; bq = q; }
            bv[k] = best;
            bi[k] = si[bq];
            sv[bq] = NEG_INF;
        }
    }
    __syncthreads();
    float hv = h[(size_t)i * HH + t];
#pragma unroll
    for (int k = 0; k < KTOP; k++) {
        int j = bi[k];
        float v = bv[k];
        atomicAdd(&hidden2[(size_t)j * HH + t], v * hv);
        if (t == 0) atomicAdd(&colsum2[j], v);
    }
}

__global__ void zero_kernel(float* __restrict__ a, int n) {
    int i = blockIdx.x * blockDim.x + threadIdx.x;
    if (i < n) a[i] = 0.0f;
}

__global__ void diag_valid_kernel(const float* __restrict__ colsum2, const float* __restrict__ diag,
                                  const float* __restrict__ h, float* __restrict__ hidden2,
                                  float* __restrict__ valid2f, float* __restrict__ norm2) {
    int j = blockIdx.x;
    int t = threadIdx.x;
    float dterm = (colsum2[j] != 0.0f) ? diag[j] : 0.0f;
    float v = hidden2[(size_t)j * HH + t] + dterm * h[(size_t)j * HH + t];
    __shared__ float shs[128];
    __shared__ float shq[128];
    shs[t] = v;
    shq[t] = v * v;
    __syncthreads();
    for (int o = 64; o > 0; o >>= 1) {
        if (t < o) { shs[t] += shs[t + o]; shq[t] += shq[t + o]; }
        __syncthreads();
    }
    float valid = (shs[0] != 0.0f) ? 1.0f : 0.0f;
    hidden2[(size_t)j * HH + t] = v * valid;
    if (t == 0) {
        valid2f[j] = valid;
        norm2[j] = valid * sqrtf(shq[0]);
    }
}

__global__ void final_kernel(const float* __restrict__ outsum, const float* __restrict__ Wout,
                             const float* __restrict__ bout, float* __restrict__ y) {
    int i = blockIdx.x;
    int t = threadIdx.x;
    __shared__ float sh[128];
    sh[t] = outsum[(size_t)i * HH + t] * Wout[t];
    __syncthreads();
    for (int o = 64; o > 0; o >>= 1) {
        if (t < o) sh[t] += sh[t + o];
        __syncthreads();
    }
    if (t == 0) y[i] = sh[0] + bout[0];
}

// ---------------- host orchestration ----------------
static EpiParams ep_make(int mode) {
    EpiParams e;
    e.mode = mode; e.accum = 0;
    e.bias = nullptr; e.normA = nullptr; e.normB = nullptr;
    e.validf = nullptr; e.resid = nullptr;
    return e;
}

static void launch_gemm64(int TA, int TB, const float* A, const float* B, float* C,
                          int M, int Nn, int K, const EpiParams& ep) {
    dim3 grid(Nn / BN, M / BM), block(256);
    if (TA == 0 && TB == 0) gemm_kernel<0, 0><<<grid, block>>>(A, B, C, M, Nn, K, ep);
    else if (TA == 0 && TB == 1) gemm_kernel<0, 1><<<grid, block>>>(A, B, C, M, Nn, K, ep);
    else if (TA == 1 && TB == 1) gemm_kernel<1, 1><<<grid, block>>>(A, B, C, M, Nn, K, ep);
    else gemm_kernel<1, 0><<<grid, block>>>(A, B, C, M, Nn, K, ep);
}

static void launch_mma(const __nv_bfloat16* A, const __nv_bfloat16* B, float* C,
                       int M, int Nn, int Ktot, int splits, const EpiParams& ep) {
    dim3 grid(Nn / 128, M / 128, splits), block(256);
    mma_gemm<<<grid, block>>>(A, B, C, M, Nn, Ktot, Ktot / splits, ep);
}

#define SYM(p, s) do { void* _tmp; cudaGetSymbolAddress(&_tmp, s); p = (float*)_tmp; } while (0)
#define SYMB(p, s) do { void* _tmp; cudaGetSymbolAddress(&_tmp, s); p = (__nv_bfloat16*)_tmp; } while (0)

extern "C" void kernel_launch(void* const* d_in, const int* in_sizes, int n_in,
                              void* d_out, int out_size) {
    const float* x = (const float*)d_in[0];
    const float* cm = (const float*)d_in[1];
    const float* mv = (const float*)d_in[2];
    const float* W_ps = (const float*)d_in[3];
    const float* b_ps = (const float*)d_in[4];
    const float* W_psf = (const float*)d_in[5];
    const float* b_psf = (const float*)d_in[6];
    const float* W_psb = (const float*)d_in[7];
    const float* b_psb = (const float*)d_in[8];
    const float* W_hs = (const float*)d_in[9];
    const float* b_hs = (const float*)d_in[10];
    const float* W_hsf = (const float*)d_in[11];
    const float* b_hsf = (const float*)d_in[12];
    const float* W_hsb = (const float*)d_in[13];
    const float* b_hsb = (const float*)d_in[14];
    const float* W_in = (const float*)d_in[15];
    const float* b_in = (const float*)d_in[16];
    const float* W_out = (const float*)d_in[17];
    const float* b_out = (const float*)d_in[18];
    float* y = (float*)d_out;

    float *p_big, *p_nc, *p_hidden1, *p_hiddenB, *p_tmp, *p_pshared, *p_h, *p_hidden2,
        *p_hshared, *p_indiv, *p_outsum, *p_colsum, *p_valid1, *p_normx, *p_normB, *p_normh,
        *p_diag, *p_norm2, *p_valid2, *p_colsum2;
    __nv_bfloat16 *p_xA3, *p_xB3, *p_hA3, *p_hB3, *p_h1A3, *p_hBB3, *p_hBT3, *p_h2B3,
        *p_h2T3, *p_c2sA3, *p_probsA3;
    SYM(p_big, g_big); SYM(p_nc, g_nc); SYM(p_hidden1, g_hidden1); SYM(p_hiddenB, g_hiddenB);
    SYM(p_tmp, g_tmp); SYM(p_pshared, g_pshared); SYM(p_h, g_h); SYM(p_hidden2, g_hidden2);
    SYM(p_hshared, g_hshared); SYM(p_indiv, g_indiv); SYM(p_outsum, g_outsum);
    SYM(p_colsum, g_colsum); SYM(p_valid1, g_valid1); SYM(p_normx, g_normx);
    SYM(p_normB, g_normB); SYM(p_normh, g_normh); SYM(p_diag, g_diag); SYM(p_norm2, g_norm2);
    SYM(p_valid2, g_valid2); SYM(p_colsum2, g_colsum2);
    SYMB(p_xA3, g_xA3); SYMB(p_xB3, g_xB3); SYMB(p_hA3, g_hA3); SYMB(p_hB3, g_hB3);
    SYMB(p_h1A3, g_h1A3); SYMB(p_hBB3, g_hBB3); SYMB(p_hBT3, g_hBT3); SYMB(p_h2B3, g_h2B3);
    SYMB(p_h2T3, g_h2T3); SYMB(p_c2sA3, g_c2sA3); SYMB(p_probsA3, g_probsA3);

    // zero atomic accumulators
    zero_kernel<<<(CC + 255) / 256, 256>>>(p_colsum, CC);
    zero_kernel<<<(CC * HH + 255) / 256, 256>>>(p_hidden1, CC * HH);
    zero_kernel<<<(CC * HH + 255) / 256, 256>>>(p_hiddenB, CC * HH);
    zero_kernel<<<(NN * HH + 255) / 256, 256>>>(p_hidden2, NN * HH);
    zero_kernel<<<(NN + 255) / 256, 256>>>(p_colsum2, NN);

    rownorm_kernel<<<NN, 128>>>(x, p_normx, nullptr);
    split3_kernel<<<(NN * HH + 255) / 256, 256>>>(x, p_xA3, NN, HH, 1);
    split3_kernel<<<(NN * HH + 255) / 256, 256>>>(x, p_xB3, NN, HH, 0);

    // ---- ps branch ----
    colsum_cm_kernel<<<32, 256>>>(cm, mv, p_colsum);
    s2c_kernel<<<(NN * CC + 255) / 256, 256>>>(cm, mv, p_colsum, p_nc);
    {
        dim3 grid(CC / 64, 16), block(256);
        splitk_kernel<1><<<grid, block>>>(p_nc, x, p_hidden1, CC, NN, NN / 16);
    }
    rowflag_kernel<<<CC, 128>>>(p_hidden1, p_valid1);
    split3_kernel<<<(CC * HH + 255) / 256, 256>>>(p_hidden1, p_h1A3, CC, HH, 1);
    // logitsT = hidden1 @ x^T  [512,4096]
    launch_mma(p_h1A3, p_xB3, p_nc, CC, NN, 3 * HH, 1, ep_make(EP_NONE));
    softmax_kernel<<<CC, 256>>>(p_nc, NN);
    {
        dim3 grid(CC / 64, 16), block(256);
        splitk_kernel<0><<<grid, block>>>(p_nc, x, p_hiddenB, CC, NN, NN / 16);
    }
    scale_rows_kernel<<<(CC * HH + 255) / 256, 256>>>(p_hiddenB, p_valid1, CC * HH);
    rownorm_kernel<<<CC, 128>>>(p_hiddenB, p_normB, nullptr);
    split3_kernel<<<(CC * HH + 255) / 256, 256>>>(p_hiddenB, p_hBB3, CC, HH, 0);
    {
        dim3 grid(CC / 32, HH / 32), block(32, 8);
        transpose_split3_kernel<<<grid, block>>>(p_hiddenB, p_hBT3, CC);
    }
    // cos(x, hiddenB)  [4096,512]
    {
        EpiParams e = ep_make(EP_COS);
        e.normA = p_normx; e.normB = p_normB; e.validf = p_valid1;
        launch_mma(p_xA3, p_hBB3, p_nc, NN, CC, 3 * HH, 1, e);
    }
    softmax_kernel<<<NN, 256>>>(p_nc, CC);
    split3_kernel<<<(NN * CC + 255) / 256, 256>>>(p_nc, p_c2sA3, NN, CC, 1);
    // tmp = c2s @ hiddenB  [4096,128]
    launch_mma(p_c2sA3, p_hBT3, p_tmp, NN, HH, 3 * CC, 1, ep_make(EP_NONE));
    {
        EpiParams e = ep_make(EP_BIAS);
        e.bias = b_ps;
        launch_gemm64(0, 0, p_tmp, W_ps, p_pshared, NN, HH, HH, e);
    }
    {
        EpiParams e = ep_make(EP_RESID);
        e.bias = b_psb; e.resid = x;
        launch_gemm64(0, 0, p_pshared, W_psb, p_h, NN, HH, HH, e);
    }
    {
        EpiParams e = ep_make(EP_BIAS_LRELU);
        e.bias = b_psf; e.accum = 0;
        launch_gemm64(0, 0, p_pshared, W_psf, p_outsum, NN, HH, HH, e);
    }

    // ---- hs branch ----
    rownorm_kernel<<<NN, 128>>>(p_h, p_normh, p_diag);
    split3_kernel<<<(NN * HH + 255) / 256, 256>>>(p_h, p_hA3, NN, HH, 1);
    split3_kernel<<<(NN * HH + 255) / 256, 256>>>(p_h, p_hB3, NN, HH, 0);
    // cos(h,h)  [4096,4096]
    {
        EpiParams e = ep_make(EP_COS);
        e.normA = p_normh; e.normB = p_normh;
        launch_mma(p_hA3, p_hB3, p_big, NN, NN, 3 * HH, 1, e);
    }
    top3_scatter_kernel<<<NN, 128>>>(p_big, p_h, p_hidden2, p_colsum2);
    diag_valid_kernel<<<NN, 128>>>(p_colsum2, p_diag, p_h, p_hidden2, p_valid2, p_norm2);
    split3_kernel<<<(NN * HH + 255) / 256, 256>>>(p_hidden2, p_h2B3, NN, HH, 0);
    {
        dim3 grid(NN / 32, HH / 32), block(32, 8);
        transpose_split3_kernel<<<grid, block>>>(p_hidden2, p_h2T3, NN);
    }
    // cos(h, hidden2)  [4096,4096]
    {
        EpiParams e = ep_make(EP_COS);
        e.normA = p_normh; e.normB = p_norm2; e.validf = p_valid2;
        launch_mma(p_hA3, p_h2B3, p_big, NN, NN, 3 * HH, 1, e);
    }
    softmax_kernel<<<NN, 256>>>(p_big, NN);
    split3_kernel<<<65536, 256>>>(p_big, p_probsA3, NN, NN, 1);
    zero_kernel<<<(NN * HH + 255) / 256, 256>>>(p_tmp, NN * HH);
    // tmp = hc2s @ hidden2  [4096,128], split-K 8, atomic epilogue
    launch_mma(p_probsA3, p_h2T3, p_tmp, NN, HH, 3 * NN, 8, ep_make(EP_ATOM));
    {
        EpiParams e = ep_make(EP_BIAS);
        e.bias = b_hs;
        launch_gemm64(0, 0, p_tmp, W_hs, p_hshared, NN, HH, HH, e);
    }
    {
        EpiParams e = ep_make(EP_RESID);
        e.bias = b_hsb; e.resid = p_h;
        launch_gemm64(0, 0, p_hshared, W_hsb, p_indiv, NN, HH, HH, e);
    }
    {
        EpiParams e = ep_make(EP_BIAS_LRELU);
        e.bias = b_hsf; e.accum = 1;
        launch_gemm64(0, 0, p_hshared, W_hsf, p_outsum, NN, HH, HH, e);
    }
    {
        EpiParams e = ep_make(EP_BIAS_LRELU);
        e.bias = b_in; e.accum = 1;
        launch_gemm64(0, 0, p_indiv, W_in, p_outsum, NN, HH, HH, e);
    }

    final_kernel<<<NN, 128>>>(p_outsum, W_out, b_out, y);
}

// round 5
// speedup vs baseline: 2.2331x; 1.0909x over previous
#include <cuda_runtime.h>
#include <cuda_bf16.h>
#include <math.h>
#include <stdint.h>

#define NN 4096
#define CC 512
#define HH 128
#define KTOP 3

#define NEG_INF (__int_as_float(0xff800000))

// ---------------- static scratch ----------------
__device__ float g_big[(size_t)NN * NN];
__device__ float g_nc[(size_t)NN * CC];
__device__ float g_hidden1[CC * HH];
__device__ float g_hiddenB[CC * HH];
__device__ float g_tmp[NN * HH];
__device__ float g_pshared[NN * HH];
__device__ float g_h[NN * HH];
__device__ float g_hidden2[NN * HH];
__device__ float g_hshared[NN * HH];
__device__ float g_indiv[NN * HH];
__device__ float g_outsum[NN * HH];
__device__ float g_colsum[CC];
__device__ float g_valid1[CC];
__device__ float g_normx[NN];
__device__ float g_normB[CC];
__device__ float g_normh[NN];
__device__ float g_diag[NN];
__device__ float g_norm2[NN];
__device__ float g_valid2[NN];
__device__ float g_colsum2[NN];
// top3 candidates: [NN rows][128 chunks][3]
__device__ float g_cval[(size_t)NN * 128 * 3];
__device__ int   g_cidx[(size_t)NN * 128 * 3];

// bf16 split-3 buffers
__device__ __nv_bfloat16 g_xA3[(size_t)NN * 3 * HH];
__device__ __nv_bfloat16 g_xB3[(size_t)NN * 3 * HH];
__device__ __nv_bfloat16 g_hA3[(size_t)NN * 3 * HH];
__device__ __nv_bfloat16 g_hB3[(size_t)NN * 3 * HH];
__device__ __nv_bfloat16 g_h1A3[(size_t)CC * 3 * HH];
__device__ __nv_bfloat16 g_hBB3[(size_t)CC * 3 * HH];
__device__ __nv_bfloat16 g_hBT3[(size_t)HH * 3 * CC];
__device__ __nv_bfloat16 g_h2B3[(size_t)NN * 3 * HH];
__device__ __nv_bfloat16 g_h2T3[(size_t)HH * 3 * NN];
__device__ __nv_bfloat16 g_c2sA3[(size_t)NN * 3 * CC];
__device__ __nv_bfloat16 g_probsA3[(size_t)NN * 3 * NN];

enum { EP_NONE = 0, EP_BIAS = 1, EP_BIAS_LRELU = 2, EP_COS = 3, EP_RESID = 5, EP_ATOM = 6,
       EP_TOP3 = 7 };

struct EpiParams {
    int mode;
    int accum;
    const float* bias;
    const float* normA;
    const float* normB;
    const float* validf;
    const float* resid;
    float* cval;
    int* cidx;
};

__device__ __forceinline__ void ins3(float v, int j, float& b0, float& b1, float& b2,
                                     int& j0, int& j1, int& j2) {
    if (v > b0) { b2 = b1; j2 = j1; b1 = b0; j1 = j0; b0 = v; j0 = j; }
    else if (v > b1) { b2 = b1; j2 = j1; b1 = v; j1 = j; }
    else if (v > b2) { b2 = v; j2 = j; }
}

// ---------------- mma.sync bf16 GEMM ----------------
#define SMEM_ROW 80

__device__ __forceinline__ void mma16816(float* c, const uint32_t* a, const uint32_t* b) {
    asm volatile(
        "mma.sync.aligned.m16n8k16.row.col.f32.bf16.bf16.f32 "
        "{%0,%1,%2,%3}, {%4,%5,%6,%7}, {%8,%9}, {%0,%1,%2,%3};"
        : "+f"(c[0]), "+f"(c[1]), "+f"(c[2]), "+f"(c[3])
        : "r"(a[0]), "r"(a[1]), "r"(a[2]), "r"(a[3]), "r"(b[0]), "r"(b[1]));
}

__device__ __forceinline__ void cp_async16(uint32_t smem_addr, const void* gptr) {
    asm volatile("cp.async.cg.shared.global [%0], [%1], 16;" :: "r"(smem_addr), "l"(gptr));
}

__global__ void __launch_bounds__(256)
mma_gemm(const __nv_bfloat16* __restrict__ A, const __nv_bfloat16* __restrict__ B,
         float* __restrict__ C, int M, int Nn, int Ktot, int kchunk, EpiParams ep) {
    __shared__ __align__(16) char As_[2][128 * SMEM_ROW];
    __shared__ __align__(16) char Bs_[2][128 * SMEM_ROW];

    const int tid = threadIdx.x;
    const int lane = tid & 31;
    const int wid = tid >> 5;
    const int warp_m = (wid >> 2) * 64;
    const int warp_n = (wid & 3) * 32;
    const int m0 = blockIdx.y * 128;
    const int n0 = blockIdx.x * 128;
    const int kbase = blockIdx.z * kchunk;
    const int niter = kchunk >> 5;

    const char* Ag = (const char*)(A + (size_t)m0 * Ktot + kbase);
    const char* Bg = (const char*)(B + (size_t)n0 * Ktot + kbase);
    const size_t rowb = (size_t)Ktot * 2;

    uint32_t asb = (uint32_t)__cvta_generic_to_shared(&As_[0][0]);
    uint32_t bsb = (uint32_t)__cvta_generic_to_shared(&Bs_[0][0]);

    float acc[4][4][4];
#pragma unroll
    for (int i = 0; i < 4; i++)
#pragma unroll
        for (int j = 0; j < 4; j++)
#pragma unroll
            for (int q = 0; q < 4; q++) acc[i][j][q] = 0.0f;

    const int lm0 = tid >> 2;
    const int lc = tid & 3;

#define LOAD_TILE(s, it) do { \
    size_t goff = (size_t)(it) * 64 + lc * 16; \
    uint32_t soff = (uint32_t)((s) * 128 * SMEM_ROW + lc * 16); \
    cp_async16(asb + soff + lm0 * SMEM_ROW, Ag + (size_t)lm0 * rowb + goff); \
    cp_async16(asb + soff + (lm0 + 64) * SMEM_ROW, Ag + (size_t)(lm0 + 64) * rowb + goff); \
    cp_async16(bsb + soff + lm0 * SMEM_ROW, Bg + (size_t)lm0 * rowb + goff); \
    cp_async16(bsb + soff + (lm0 + 64) * SMEM_ROW, Bg + (size_t)(lm0 + 64) * rowb + goff); \
    asm volatile("cp.async.commit_group;"); \
} while (0)

    LOAD_TILE(0, 0);

    for (int it = 0; it < niter; it++) {
        int s = it & 1;
        if (it + 1 < niter) {
            LOAD_TILE(s ^ 1, it + 1);
            asm volatile("cp.async.wait_group 1;");
        } else {
            asm volatile("cp.async.wait_group 0;");
        }
        __syncthreads();

        const char* Asb = As_[s];
        const char* Bsb = Bs_[s];
#pragma unroll
        for (int ks = 0; ks < 32; ks += 16) {
            uint32_t a[4][4], b[4][2];
            int cb2 = (ks + (lane & 3) * 2) * 2;
#pragma unroll
            for (int mi = 0; mi < 4; mi++) {
                int r = warp_m + mi * 16 + (lane >> 2);
                a[mi][0] = *(const uint32_t*)(Asb + r * SMEM_ROW + cb2);
                a[mi][1] = *(const uint32_t*)(Asb + (r + 8) * SMEM_ROW + cb2);
                a[mi][2] = *(const uint32_t*)(Asb + r * SMEM_ROW + cb2 + 16);
                a[mi][3] = *(const uint32_t*)(Asb + (r + 8) * SMEM_ROW + cb2 + 16);
            }
#pragma unroll
            for (int ni = 0; ni < 4; ni++) {
                int rn = warp_n + ni * 8 + (lane >> 2);
                b[ni][0] = *(const uint32_t*)(Bsb + rn * SMEM_ROW + cb2);
                b[ni][1] = *(const uint32_t*)(Bsb + rn * SMEM_ROW + cb2 + 16);
            }
#pragma unroll
            for (int mi = 0; mi < 4; mi++)
#pragma unroll
                for (int ni = 0; ni < 4; ni++) mma16816(acc[mi][ni], a[mi], b[ni]);
        }
        __syncthreads();
    }

    if (ep.mode == EP_TOP3) {
        // per-row top3 within this warp's 32-col chunk, via quad shuffles
#pragma unroll
        for (int mi = 0; mi < 4; mi++) {
#pragma unroll
            for (int half = 0; half < 2; half++) {
                int m = m0 + warp_m + mi * 16 + (lane >> 2) + half * 8;
                float na = ep.normA[m];
                float b0 = NEG_INF, b1 = NEG_INF, b2 = NEG_INF;
                int j0 = 0, j1 = 0, j2 = 0;
#pragma unroll
                for (int ni = 0; ni < 4; ni++) {
#pragma unroll
                    for (int q = 0; q < 2; q++) {
                        int c = n0 + warp_n + ni * 8 + (lane & 3) * 2 + q;
                        float v = acc[mi][ni][half * 2 + q];
                        float den = na * ep.normB[c];
                        v = v / (den == 0.0f ? 1.0f : den);
                        if (c == m) v = NEG_INF;
                        ins3(v, c, b0, b1, b2, j0, j1, j2);
                    }
                }
#pragma unroll
                for (int msk = 1; msk <= 2; msk <<= 1) {
                    float o0 = __shfl_xor_sync(0xffffffff, b0, msk);
                    int p0 = __shfl_xor_sync(0xffffffff, j0, msk);
                    float o1 = __shfl_xor_sync(0xffffffff, b1, msk);
                    int p1 = __shfl_xor_sync(0xffffffff, j1, msk);
                    float o2 = __shfl_xor_sync(0xffffffff, b2, msk);
                    int p2 = __shfl_xor_sync(0xffffffff, j2, msk);
                    ins3(o0, p0, b0, b1, b2, j0, j1, j2);
                    ins3(o1, p1, b0, b1, b2, j0, j1, j2);
                    ins3(o2, p2, b0, b1, b2, j0, j1, j2);
                }
                if ((lane & 3) == 0) {
                    int chunk = blockIdx.x * 4 + (warp_n >> 5);
                    size_t off = ((size_t)m * 128 + chunk) * 3;
                    ep.cval[off] = b0; ep.cval[off + 1] = b1; ep.cval[off + 2] = b2;
                    ep.cidx[off] = j0; ep.cidx[off + 1] = j1; ep.cidx[off + 2] = j2;
                }
            }
        }
        return;
    }

#pragma unroll
    for (int mi = 0; mi < 4; mi++) {
        int r0 = m0 + warp_m + mi * 16 + (lane >> 2);
#pragma unroll
        for (int ni = 0; ni < 4; ni++) {
            int c = n0 + warp_n + ni * 8 + (lane & 3) * 2;
#pragma unroll
            for (int half = 0; half < 2; half++) {
                int m = r0 + half * 8;
                float v0 = acc[mi][ni][half * 2];
                float v1 = acc[mi][ni][half * 2 + 1];
                size_t o = (size_t)m * Nn + c;
                if (ep.mode == EP_COS) {
                    float na = ep.normA[m];
                    float d0 = na * ep.normB[c];
                    float d1 = na * ep.normB[c + 1];
                    v0 = v0 / (d0 == 0.0f ? 1.0f : d0);
                    v1 = v1 / (d1 == 0.0f ? 1.0f : d1);
                    if (ep.validf) {
                        if (ep.validf[c] == 0.0f) v0 = NEG_INF;
                        if (ep.validf[c + 1] == 0.0f) v1 = NEG_INF;
                    }
                    *(float2*)&C[o] = make_float2(v0, v1);
                } else if (ep.mode == EP_ATOM) {
                    atomicAdd(&C[o], v0);
                    atomicAdd(&C[o + 1], v1);
                } else {
                    *(float2*)&C[o] = make_float2(v0, v1);
                }
            }
        }
    }
}

// ---------------- transpose split3 (B-pattern [h,l,h]) ----------------
__global__ void transpose_split3_kernel(const float* __restrict__ X,
                                        __nv_bfloat16* __restrict__ Y, int K) {
    __shared__ float tile[32][33];
    int k0 = blockIdx.x * 32, h0 = blockIdx.y * 32;
    int tx = threadIdx.x, ty = threadIdx.y;
    for (int r = ty; r < 32; r += 8)
        tile[r][tx] = X[(size_t)(k0 + r) * HH + h0 + tx];
    __syncthreads();
    for (int r = ty; r < 32; r += 8) {
        int hcol = h0 + r;
        int k = k0 + tx;
        float v = tile[tx][r];
        __nv_bfloat16 h = __float2bfloat16(v);
        __nv_bfloat16 l = __float2bfloat16(v - __bfloat162float(h));
        size_t base = (size_t)hcol * 3 * K + k;
        Y[base] = h;
        Y[base + K] = l;
        Y[base + 2 * K] = h;
    }
}

// ---------------- fp32 split-K GEMM into 128 cols ----------------
template <int TA>
__global__ void splitk_kernel(const float* __restrict__ A, const float* __restrict__ B,
                              float* __restrict__ C, int M, int K, int kchunk) {
    __shared__ float As[16][64 + 4];
    __shared__ float Bs[16][128 + 4];
    const int m0 = blockIdx.x * 64;
    const int kb = blockIdx.y * kchunk;
    const int tid = threadIdx.x;
    const int tx = tid & 15;
    const int ty = tid >> 4;

    float acc[4][8];
#pragma unroll
    for (int i = 0; i < 4; i++)
#pragma unroll
        for (int j = 0; j < 8; j++) acc[i][j] = 0.0f;

    for (int k0 = 0; k0 < kchunk; k0 += 16) {
        if (TA == 0) {
            int k4 = tid & 3;
            int m = tid >> 2;
            float4 v = *(const float4*)&A[(size_t)(m0 + m) * K + kb + k0 + k4 * 4];
            As[k4 * 4 + 0][m] = v.x;
            As[k4 * 4 + 1][m] = v.y;
            As[k4 * 4 + 2][m] = v.z;
            As[k4 * 4 + 3][m] = v.w;
        } else {
            int k = tid >> 4;
            int m4 = tid & 15;
            float4 v = *(const float4*)&A[(size_t)(kb + k0 + k) * M + m0 + m4 * 4];
            *(float4*)&As[k][m4 * 4] = v;
        }
#pragma unroll
        for (int l = 0; l < 2; l++) {
            int id = tid + l * 256;
            int n4 = id & 31;
            int k = id >> 5;
            float4 v = *(const float4*)&B[(size_t)(kb + k0 + k) * 128 + n4 * 4];
            *(float4*)&Bs[k][n4 * 4] = v;
        }
        __syncthreads();
#pragma unroll
        for (int k = 0; k < 16; k++) {
            float a[4], b[8];
#pragma unroll
            for (int i = 0; i < 4; i++) a[i] = As[k][ty * 4 + i];
#pragma unroll
            for (int j = 0; j < 8; j++) b[j] = Bs[k][tx * 8 + j];
#pragma unroll
            for (int i = 0; i < 4; i++)
#pragma unroll
                for (int j = 0; j < 8; j++) acc[i][j] = fmaf(a[i], b[j], acc[i][j]);
        }
        __syncthreads();
    }
#pragma unroll
    for (int i = 0; i < 4; i++)
#pragma unroll
        for (int j = 0; j < 8; j++)
            atomicAdd(&C[(size_t)(m0 + ty * 4 + i) * 128 + tx * 8 + j], acc[i][j]);
}

// ---------------- 64x64 fp32 GEMM for HHxHH weight layers ----------------
#define BM 64
#define BN 64
#define BK 32

template <int TA, int TB>
__global__ void gemm_kernel(const float* __restrict__ A, const float* __restrict__ B,
                            float* __restrict__ C, int M, int Nn, int K, EpiParams ep) {
    __shared__ float As[BK][BM + 4];
    __shared__ float Bs[BK][BN + 4];
    const int m0 = blockIdx.y * BM;
    const int n0 = blockIdx.x * BN;
    const int tid = threadIdx.x;
    const int tx = tid & 15;
    const int ty = tid >> 4;

    float acc[4][4];
#pragma unroll
    for (int i = 0; i < 4; i++)
#pragma unroll
        for (int j = 0; j < 4; j++) acc[i][j] = 0.0f;

    for (int k0 = 0; k0 < K; k0 += BK) {
        if (TA == 0) {
#pragma unroll
            for (int l = 0; l < 8; l++) {
                int id = tid + l * 256;
                int k = id & 31, m = id >> 5;
                As[k][m] = A[(size_t)(m0 + m) * K + (k0 + k)];
            }
        } else {
#pragma unroll
            for (int l = 0; l < 8; l++) {
                int id = tid + l * 256;
                int m = id & 63, k = id >> 6;
                As[k][m] = A[(size_t)(k0 + k) * M + (m0 + m)];
            }
        }
        if (TB == 0) {
#pragma unroll
            for (int l = 0; l < 8; l++) {
                int id = tid + l * 256;
                int k = id & 31, n = id >> 5;
                Bs[k][n] = B[(size_t)(n0 + n) * K + (k0 + k)];
            }
        } else {
#pragma unroll
            for (int l = 0; l < 8; l++) {
                int id = tid + l * 256;
                int n = id & 63, k = id >> 6;
                Bs[k][n] = B[(size_t)(k0 + k) * Nn + (n0 + n)];
            }
        }
        __syncthreads();
#pragma unroll
        for (int k = 0; k < BK; k++) {
            float a[4], b[4];
#pragma unroll
            for (int i = 0; i < 4; i++) a[i] = As[k][ty * 4 + i];
#pragma unroll
            for (int j = 0; j < 4; j++) b[j] = Bs[k][tx * 4 + j];
#pragma unroll
            for (int i = 0; i < 4; i++)
#pragma unroll
                for (int j = 0; j < 4; j++) acc[i][j] = fmaf(a[i], b[j], acc[i][j]);
        }
        __syncthreads();
    }

#pragma unroll
    for (int i = 0; i < 4; i++) {
#pragma unroll
        for (int j = 0; j < 4; j++) {
            int m = m0 + ty * 4 + i;
            int n = n0 + tx * 4 + j;
            float v = acc[i][j];
            size_t o = (size_t)m * Nn + n;
            switch (ep.mode) {
                case EP_NONE: C[o] = v; break;
                case EP_BIAS: C[o] = v + ep.bias[n]; break;
                case EP_BIAS_LRELU: {
                    float z = v + ep.bias[n];
                    z = z > 0.0f ? z : 0.01f * z;
                    if (ep.accum) C[o] += z; else C[o] = z;
                    break;
                }
                case EP_RESID: C[o] = ep.resid[o] - (v + ep.bias[n]); break;
            }
        }
    }
}

// ---------------- fused small kernels ----------------
__global__ void zero_all_kernel(float* h2, float* h1, float* hB, float* cs, float* cs2,
                                float* tmp) {
    int i = blockIdx.x * blockDim.x + threadIdx.x;   // 512K threads
    h2[i] = 0.0f;
    tmp[i] = 0.0f;
    if (i < CC * HH) { h1[i] = 0.0f; hB[i] = 0.0f; }
    if (i < CC) cs[i] = 0.0f;
    if (i < NN) cs2[i] = 0.0f;
}

__global__ void zero_kernel(float* __restrict__ a, int n) {
    int i = blockIdx.x * blockDim.x + threadIdx.x;
    if (i < n) a[i] = 0.0f;
}

// x: norm + A/B split3
__global__ void xprep_kernel(const float* __restrict__ X, float* __restrict__ norm,
                             __nv_bfloat16* __restrict__ A3, __nv_bfloat16* __restrict__ B3) {
    int m = blockIdx.x, t = threadIdx.x;
    float v = X[(size_t)m * HH + t];
    __shared__ float sh[128];
    sh[t] = v * v;
    __syncthreads();
    for (int o = 64; o > 0; o >>= 1) {
        if (t < o) sh[t] += sh[t + o];
        __syncthreads();
    }
    if (t == 0) norm[m] = sqrtf(sh[0]);
    __nv_bfloat16 h = __float2bfloat16(v);
    __nv_bfloat16 l = __float2bfloat16(v - __bfloat162float(h));
    size_t base = (size_t)m * 3 * HH + t;
    A3[base] = h; A3[base + HH] = h; A3[base + 2 * HH] = l;
    B3[base] = h; B3[base + HH] = l; B3[base + 2 * HH] = h;
}

// hidden1: rowsum -> valid1, write A-pattern split3
__global__ void hidden1post_kernel(const float* __restrict__ X, float* __restrict__ validf,
                                   __nv_bfloat16* __restrict__ A3) {
    int m = blockIdx.x, t = threadIdx.x;
    float v = X[(size_t)m * HH + t];
    __shared__ float sh[128];
    sh[t] = v;
    __syncthreads();
    for (int o = 64; o > 0; o >>= 1) {
        if (t < o) sh[t] += sh[t + o];
        __syncthreads();
    }
    if (t == 0) validf[m] = (sh[0] != 0.0f) ? 1.0f : 0.0f;
    __nv_bfloat16 h = __float2bfloat16(v);
    __nv_bfloat16 l = __float2bfloat16(v - __bfloat162float(h));
    size_t base = (size_t)m * 3 * HH + t;
    A3[base] = h; A3[base + HH] = h; A3[base + 2 * HH] = l;
}

// hiddenB: scale by valid1 (in place), norm, B-pattern split3
__global__ void hiddenBpost_kernel(float* __restrict__ X, const float* __restrict__ validf,
                                   float* __restrict__ norm, __nv_bfloat16* __restrict__ B3) {
    int m = blockIdx.x, t = threadIdx.x;
    float v = X[(size_t)m * HH + t] * validf[m];
    X[(size_t)m * HH + t] = v;
    __shared__ float sh[128];
    sh[t] = v * v;
    __syncthreads();
    for (int o = 64; o > 0; o >>= 1) {
        if (t < o) sh[t] += sh[t + o];
        __syncthreads();
    }
    if (t == 0) norm[m] = sqrtf(sh[0]);
    __nv_bfloat16 h = __float2bfloat16(v);
    __nv_bfloat16 l = __float2bfloat16(v - __bfloat162float(h));
    size_t base = (size_t)m * 3 * HH + t;
    B3[base] = h; B3[base + HH] = l; B3[base + 2 * HH] = h;
}

// h: norm + diag + A/B split3
__global__ void hpost_kernel(const float* __restrict__ X, float* __restrict__ norm,
                             float* __restrict__ diag, __nv_bfloat16* __restrict__ A3,
                             __nv_bfloat16* __restrict__ B3) {
    int m = blockIdx.x, t = threadIdx.x;
    float v = X[(size_t)m * HH + t];
    __shared__ float sh[128];
    sh[t] = v * v;
    __syncthreads();
    for (int o = 64; o > 0; o >>= 1) {
        if (t < o) sh[t] += sh[t + o];
        __syncthreads();
    }
    if (t == 0) {
        float ss = sh[0];
        float n = sqrtf(ss);
        norm[m] = n;
        float den = n * n;
        diag[m] = (den == 0.0f) ? 0.0f : ss / den;
    }
    __nv_bfloat16 h = __float2bfloat16(v);
    __nv_bfloat16 l = __float2bfloat16(v - __bfloat162float(h));
    size_t base = (size_t)m * 3 * HH + t;
    A3[base] = h; A3[base + HH] = h; A3[base + 2 * HH] = l;
    B3[base] = h; B3[base + HH] = l; B3[base + 2 * HH] = h;
}

// plain fp32 in-place softmax (for logitsT)
__global__ void softmax_kernel(float* __restrict__ buf, int L) {
    int r = blockIdx.x;
    float* row = buf + (size_t)r * L;
    int t = threadIdx.x;
    int V = L >> 8;
    float v[16];
    float mx = NEG_INF;
    for (int u = 0; u < V; u++) {
        v[u] = row[t + (u << 8)];
        mx = fmaxf(mx, v[u]);
    }
    __shared__ float sh[256];
    sh[t] = mx;
    __syncthreads();
    for (int o = 128; o > 0; o >>= 1) {
        if (t < o) sh[t] = fmaxf(sh[t], sh[t + o]);
        __syncthreads();
    }
    mx = sh[0];
    __syncthreads();
    float s = 0.0f;
    for (int u = 0; u < V; u++) {
        v[u] = expf(v[u] - mx);
        s += v[u];
    }
    sh[t] = s;
    __syncthreads();
    for (int o = 128; o > 0; o >>= 1) {
        if (t < o) sh[t] += sh[t + o];
        __syncthreads();
    }
    float inv = 1.0f / sh[0];
    for (int u = 0; u < V; u++) row[t + (u << 8)] = v[u] * inv;
}

// softmax writing bf16 split-3 A-pattern directly (no fp32 writeback)
__global__ void softmax_split3_kernel(const float* __restrict__ buf,
                                      __nv_bfloat16* __restrict__ out3, int L) {
    int r = blockIdx.x;
    const float* row = buf + (size_t)r * L;
    __nv_bfloat16* orow = out3 + (size_t)r * 3 * L;
    int t = threadIdx.x;
    int V = L >> 8;
    float v[16];
    float mx = NEG_INF;
    for (int u = 0; u < V; u++) {
        v[u] = row[t + (u << 8)];
        mx = fmaxf(mx, v[u]);
    }
    __shared__ float sh[256];
    sh[t] = mx;
    __syncthreads();
    for (int o = 128; o > 0; o >>= 1) {
        if (t < o) sh[t] = fmaxf(sh[t], sh[t + o]);
        __syncthreads();
    }
    mx = sh[0];
    __syncthreads();
    float s = 0.0f;
    for (int u = 0; u < V; u++) {
        v[u] = expf(v[u] - mx);
        s += v[u];
    }
    sh[t] = s;
    __syncthreads();
    for (int o = 128; o > 0; o >>= 1) {
        if (t < o) sh[t] += sh[t + o];
        __syncthreads();
    }
    float inv = 1.0f / sh[0];
    for (int u = 0; u < V; u++) {
        float p = v[u] * inv;
        __nv_bfloat16 h = __float2bfloat16(p);
        __nv_bfloat16 l = __float2bfloat16(p - __bfloat162float(h));
        int c = t + (u << 8);
        orow[c] = h;
        orow[c + L] = h;
        orow[c + 2 * L] = l;
    }
}

// reduce 128-chunk candidates to global top3, then scatter
__global__ void top3_reduce_scatter(const float* __restrict__ cval, const int* __restrict__ cidx,
                                    const float* __restrict__ h, float* __restrict__ hidden2,
                                    float* __restrict__ colsum2) {
    int i = blockIdx.x, t = threadIdx.x;  // 128 threads
    size_t off = ((size_t)i * 128 + t) * 3;
    __shared__ float sv[384];
    __shared__ int si[384];
    __shared__ float bv[KTOP];
    __shared__ int bi[KTOP];
    sv[t] = cval[off]; sv[128 + t] = cval[off + 1]; sv[256 + t] = cval[off + 2];
    si[t] = cidx[off]; si[128 + t] = cidx[off + 1]; si[256 + t] = cidx[off + 2];
    __syncthreads();
    if (t == 0) {
        float a0 = NEG_INF, a1 = NEG_INF, a2 = NEG_INF;
        int j0 = 0, j1 = 0, j2 = 0;
        for (int q = 0; q < 384; q++) ins3(sv[q], si[q], a0, a1, a2, j0, j1, j2);
        ins3(0.0f, i, a0, a1, a2, j0, j1, j2);  // diag candidate (masked value 0)
        bv[0] = a0; bv[1] = a1; bv[2] = a2;
        bi[0] = j0; bi[1] = j1; bi[2] = j2;
    }
    __syncthreads();
    float hv = h[(size_t)i * HH + t];
#pragma unroll
    for (int k = 0; k < KTOP; k++) {
        int j = bi[k];
        float v = bv[k];
        atomicAdd(&hidden2[(size_t)j * HH + t], v * hv);
        if (t == 0) atomicAdd(&colsum2[j], v);
    }
}

__global__ void colsum_cm_kernel(const float* __restrict__ cm, const float* __restrict__ mv,
                                 float* __restrict__ colsum) {
    int b = blockIdx.x;
    int t = threadIdx.x;
    float s0 = 0.0f, s1 = 0.0f;
    for (int rr = 0; rr < 128; rr++) {
        int r = b * 128 + rr;
        float m = mv[r];
        s0 += cm[(size_t)r * CC + t] * m;
        s1 += cm[(size_t)r * CC + 256 + t] * m;
    }
    atomicAdd(&colsum[t], s0);
    atomicAdd(&colsum[t + 256], s1);
}

__global__ void s2c_kernel(const float* __restrict__ cm, const float* __restrict__ mv,
                           const float* __restrict__ colsum, float* __restrict__ out) {
    int idx = blockIdx.x * blockDim.x + threadIdx.x;
    if (idx >= NN * CC) return;
    int i = idx / CC;
    int c = idx - i * CC;
    float m = cm[idx];
    out[idx] = (m * mv[i]) / (colsum[c] * m + 1.0f);
}

// diag add + valid2 + norm2 + B-pattern split3 of hidden2
__global__ void diag_valid_kernel(const float* __restrict__ colsum2, const float* __restrict__ diag,
                                  const float* __restrict__ h, float* __restrict__ hidden2,
                                  float* __restrict__ valid2f, float* __restrict__ norm2,
                                  __nv_bfloat16* __restrict__ B3) {
    int j = blockIdx.x;
    int t = threadIdx.x;
    float dterm = (colsum2[j] != 0.0f) ? diag[j] : 0.0f;
    float v = hidden2[(size_t)j * HH + t] + dterm * h[(size_t)j * HH + t];
    __shared__ float shs[128];
    __shared__ float shq[128];
    shs[t] = v;
    shq[t] = v * v;
    __syncthreads();
    for (int o = 64; o > 0; o >>= 1) {
        if (t < o) { shs[t] += shs[t + o]; shq[t] += shq[t + o]; }
        __syncthreads();
    }
    float valid = (shs[0] != 0.0f) ? 1.0f : 0.0f;
    v *= valid;
    hidden2[(size_t)j * HH + t] = v;
    if (t == 0) {
        valid2f[j] = valid;
        norm2[j] = valid * sqrtf(shq[0]);
    }
    __nv_bfloat16 hh = __float2bfloat16(v);
    __nv_bfloat16 l = __float2bfloat16(v - __bfloat162float(hh));
    size_t base = (size_t)j * 3 * HH + t;
    B3[base] = hh; B3[base + HH] = l; B3[base + 2 * HH] = hh;
}

__global__ void final_kernel(const float* __restrict__ outsum, const float* __restrict__ Wout,
                             const float* __restrict__ bout, float* __restrict__ y) {
    int i = blockIdx.x;
    int t = threadIdx.x;
    __shared__ float sh[128];
    sh[t] = outsum[(size_t)i * HH + t] * Wout[t];
    __syncthreads();
    for (int o = 64; o > 0; o >>= 1) {
        if (t < o) sh[t] += sh[t + o];
        __syncthreads();
    }
    if (t == 0) y[i] = sh[0] + bout[0];
}

// ---------------- host orchestration ----------------
static EpiParams ep_make(int mode) {
    EpiParams e;
    e.mode = mode; e.accum = 0;
    e.bias = nullptr; e.normA = nullptr; e.normB = nullptr;
    e.validf = nullptr; e.resid = nullptr; e.cval = nullptr; e.cidx = nullptr;
    return e;
}

static void launch_gemm64(int TA, int TB, const float* A, const float* B, float* C,
                          int M, int Nn, int K, const EpiParams& ep) {
    dim3 grid(Nn / BN, M / BM), block(256);
    if (TA == 0 && TB == 0) gemm_kernel<0, 0><<<grid, block>>>(A, B, C, M, Nn, K, ep);
    else if (TA == 0 && TB == 1) gemm_kernel<0, 1><<<grid, block>>>(A, B, C, M, Nn, K, ep);
    else if (TA == 1 && TB == 1) gemm_kernel<1, 1><<<grid, block>>>(A, B, C, M, Nn, K, ep);
    else gemm_kernel<1, 0><<<grid, block>>>(A, B, C, M, Nn, K, ep);
}

static void launch_mma(const __nv_bfloat16* A, const __nv_bfloat16* B, float* C,
                       int M, int Nn, int Ktot, int splits, const EpiParams& ep) {
    dim3 grid(Nn / 128, M / 128, splits), block(256);
    mma_gemm<<<grid, block>>>(A, B, C, M, Nn, Ktot, Ktot / splits, ep);
}

#define SYM(p, s) do { void* _tmp; cudaGetSymbolAddress(&_tmp, s); p = (float*)_tmp; } while (0)
#define SYMB(p, s) do { void* _tmp; cudaGetSymbolAddress(&_tmp, s); p = (__nv_bfloat16*)_tmp; } while (0)

extern "C" void kernel_launch(void* const* d_in, const int* in_sizes, int n_in,
                              void* d_out, int out_size) {
    const float* x = (const float*)d_in[0];
    const float* cm = (const float*)d_in[1];
    const float* mv = (const float*)d_in[2];
    const float* W_ps = (const float*)d_in[3];
    const float* b_ps = (const float*)d_in[4];
    const float* W_psf = (const float*)d_in[5];
    const float* b_psf = (const float*)d_in[6];
    const float* W_psb = (const float*)d_in[7];
    const float* b_psb = (const float*)d_in[8];
    const float* W_hs = (const float*)d_in[9];
    const float* b_hs = (const float*)d_in[10];
    const float* W_hsf = (const float*)d_in[11];
    const float* b_hsf = (const float*)d_in[12];
    const float* W_hsb = (const float*)d_in[13];
    const float* b_hsb = (const float*)d_in[14];
    const float* W_in = (const float*)d_in[15];
    const float* b_in = (const float*)d_in[16];
    const float* W_out = (const float*)d_in[17];
    const float* b_out = (const float*)d_in[18];
    float* y = (float*)d_out;

    float *p_big, *p_nc, *p_hidden1, *p_hiddenB, *p_tmp, *p_pshared, *p_h, *p_hidden2,
        *p_hshared, *p_indiv, *p_outsum, *p_colsum, *p_valid1, *p_normx, *p_normB, *p_normh,
        *p_diag, *p_norm2, *p_valid2, *p_colsum2, *p_cval;
    int* p_cidx;
    __nv_bfloat16 *p_xA3, *p_xB3, *p_hA3, *p_hB3, *p_h1A3, *p_hBB3, *p_hBT3, *p_h2B3,
        *p_h2T3, *p_c2sA3, *p_probsA3;
    SYM(p_big, g_big); SYM(p_nc, g_nc); SYM(p_hidden1, g_hidden1); SYM(p_hiddenB, g_hiddenB);
    SYM(p_tmp, g_tmp); SYM(p_pshared, g_pshared); SYM(p_h, g_h); SYM(p_hidden2, g_hidden2);
    SYM(p_hshared, g_hshared); SYM(p_indiv, g_indiv); SYM(p_outsum, g_outsum);
    SYM(p_colsum, g_colsum); SYM(p_valid1, g_valid1); SYM(p_normx, g_normx);
    SYM(p_normB, g_normB); SYM(p_normh, g_normh); SYM(p_diag, g_diag); SYM(p_norm2, g_norm2);
    SYM(p_valid2, g_valid2); SYM(p_colsum2, g_colsum2); SYM(p_cval, g_cval);
    { void* t; cudaGetSymbolAddress(&t, g_cidx); p_cidx = (int*)t; }
    SYMB(p_xA3, g_xA3); SYMB(p_xB3, g_xB3); SYMB(p_hA3, g_hA3); SYMB(p_hB3, g_hB3);
    SYMB(p_h1A3, g_h1A3); SYMB(p_hBB3, g_hBB3); SYMB(p_hBT3, g_hBT3); SYMB(p_h2B3, g_h2B3);
    SYMB(p_h2T3, g_h2T3); SYMB(p_c2sA3, g_c2sA3); SYMB(p_probsA3, g_probsA3);

    zero_all_kernel<<<NN * HH / 256, 256>>>(p_hidden2, p_hidden1, p_hiddenB, p_colsum,
                                            p_colsum2, p_tmp);
    xprep_kernel<<<NN, 128>>>(x, p_normx, p_xA3, p_xB3);

    // ---- ps branch ----
    colsum_cm_kernel<<<32, 256>>>(cm, mv, p_colsum);
    s2c_kernel<<<(NN * CC + 255) / 256, 256>>>(cm, mv, p_colsum, p_nc);
    {
        dim3 grid(CC / 64, 16), block(256);
        splitk_kernel<1><<<grid, block>>>(p_nc, x, p_hidden1, CC, NN, NN / 16);
    }
    hidden1post_kernel<<<CC, 128>>>(p_hidden1, p_valid1, p_h1A3);
    // logitsT = hidden1 @ x^T  [512,4096]
    launch_mma(p_h1A3, p_xB3, p_nc, CC, NN, 3 * HH, 1, ep_make(EP_NONE));
    softmax_kernel<<<CC, 256>>>(p_nc, NN);
    {
        dim3 grid(CC / 64, 16), block(256);
        splitk_kernel<0><<<grid, block>>>(p_nc, x, p_hiddenB, CC, NN, NN / 16);
    }
    hiddenBpost_kernel<<<CC, 128>>>(p_hiddenB, p_valid1, p_normB, p_hBB3);
    {
        dim3 grid(CC / 32, HH / 32), block(32, 8);
        transpose_split3_kernel<<<grid, block>>>(p_hiddenB, p_hBT3, CC);
    }
    // cos(x, hiddenB)  [4096,512]
    {
        EpiParams e = ep_make(EP_COS);
        e.normA = p_normx; e.normB = p_normB; e.validf = p_valid1;
        launch_mma(p_xA3, p_hBB3, p_nc, NN, CC, 3 * HH, 1, e);
    }
    softmax_split3_kernel<<<NN, 256>>>(p_nc, p_c2sA3, CC);
    // tmp = c2s @ hiddenB  [4096,128], split-K 4, atomic (tmp pre-zeroed)
    launch_mma(p_c2sA3, p_hBT3, p_tmp, NN, HH, 3 * CC, 4, ep_make(EP_ATOM));
    {
        EpiParams e = ep_make(EP_BIAS);
        e.bias = b_ps;
        launch_gemm64(0, 0, p_tmp, W_ps, p_pshared, NN, HH, HH, e);
    }
    {
        EpiParams e = ep_make(EP_RESID);
        e.bias = b_psb; e.resid = x;
        launch_gemm64(0, 0, p_pshared, W_psb, p_h, NN, HH, HH, e);
    }
    {
        EpiParams e = ep_make(EP_BIAS_LRELU);
        e.bias = b_psf; e.accum = 0;
        launch_gemm64(0, 0, p_pshared, W_psf, p_outsum, NN, HH, HH, e);
    }

    // ---- hs branch ----
    hpost_kernel<<<NN, 128>>>(p_h, p_normh, p_diag, p_hA3, p_hB3);
    // cos(h,h) with fused per-chunk top3 (no NN*NN materialization)
    {
        EpiParams e = ep_make(EP_TOP3);
        e.normA = p_normh; e.normB = p_normh;
        e.cval = p_cval; e.cidx = p_cidx;
        launch_mma(p_hA3, p_hB3, p_big, NN, NN, 3 * HH, 1, e);
    }
    top3_reduce_scatter<<<NN, 128>>>(p_cval, p_cidx, p_h, p_hidden2, p_colsum2);
    diag_valid_kernel<<<NN, 128>>>(p_colsum2, p_diag, p_h, p_hidden2, p_valid2, p_norm2,
                                   p_h2B3);
    {
        dim3 grid(NN / 32, HH / 32), block(32, 8);
        transpose_split3_kernel<<<grid, block>>>(p_hidden2, p_h2T3, NN);
    }
    // cos(h, hidden2)  [4096,4096]
    {
        EpiParams e = ep_make(EP_COS);
        e.normA = p_normh; e.normB = p_norm2; e.validf = p_valid2;
        launch_mma(p_hA3, p_h2B3, p_big, NN, NN, 3 * HH, 1, e);
    }
    softmax_split3_kernel<<<NN, 256>>>(p_big, p_probsA3, NN);
    zero_kernel<<<NN * HH / 256, 256>>>(p_tmp, NN * HH);
    // tmp = hc2s @ hidden2  [4096,128], split-K 8, atomic
    launch_mma(p_probsA3, p_h2T3, p_tmp, NN, HH, 3 * NN, 8, ep_make(EP_ATOM));
    {
        EpiParams e = ep_make(EP_BIAS);
        e.bias = b_hs;
        launch_gemm64(0, 0, p_tmp, W_hs, p_hshared, NN, HH, HH, e);
    }
    {
        EpiParams e = ep_make(EP_RESID);
        e.bias = b_hsb; e.resid = p_h;
        launch_gemm64(0, 0, p_hshared, W_hsb, p_indiv, NN, HH, HH, e);
    }
    {
        EpiParams e = ep_make(EP_BIAS_LRELU);
        e.bias = b_hsf; e.accum = 1;
        launch_gemm64(0, 0, p_hshared, W_hsf, p_outsum, NN, HH, HH, e);
    }
    {
        EpiParams e = ep_make(EP_BIAS_LRELU);
        e.bias = b_in; e.accum = 1;
        launch_gemm64(0, 0, p_indiv, W_in, p_outsum, NN, HH, HH, e);
    }

    final_kernel<<<NN, 128>>>(p_outsum, W_out, b_out, y);
}